// round 13
// baseline (speedup 1.0000x reference)
#include <cuda_runtime.h>
#include <cuda_bf16.h>
#include <cstdint>

#define B_  16
#define S_  80
#define D_  512
#define H_  64
#define G4_ 256    /* 4*H */
#define DI_ 2048
#define L_  6
#define M_  (B_*S_)   /* 1280 rows */
#define NS  4         /* samples per LSTM resume block */
#define SPLITK_W2 4

typedef unsigned long long ull;
typedef __nv_bfloat16 bf16;

// ---------------- scratch (static device globals; no allocation) ----------------
__device__ float  g_x [M_*D_];     // residual stream (fp32)
__device__ float  g_xg[M_*G4_];    // gate projections, layout [(s*16+b)*256+g]
__device__ float  g_y [M_*DI_];    // FFN hidden (fp32)
__device__ float  g_hf[M_*H_];     // LSTM hidden (fp32)
__device__ float  g_ckh[S_*B_*H_], g_ckc[S_*B_*H_]; // LSTM checkpoints
__device__ float  g_part[SPLITK_W2*M_*D_];          // w2 split-K partials
// int8 hi/lo quantized operands + per-row scales
__device__ int8_t g_xnq_h[M_*D_],  g_xnq_l[M_*D_];   __device__ float g_sxn[M_];
__device__ int8_t g_hq_h [M_*H_],  g_hq_l [M_*H_];   __device__ float g_shq[M_];
__device__ int8_t g_yq_h [M_*DI_], g_yq_l [M_*DI_];  __device__ float g_sy [M_];
__device__ int8_t g_wihq_h[L_*G4_*D_], g_wihq_l[L_*G4_*D_]; __device__ float g_swih[L_*G4_];
__device__ int8_t g_wfcq_h[L_*D_*H_],  g_wfcq_l[L_*D_*H_];  __device__ float g_swfc[L_*D_];
__device__ int8_t g_w1q_h[L_*DI_*D_],  g_w1q_l[L_*DI_*D_];  __device__ float g_sw1[L_*DI_];
__device__ int8_t g_w2q_h[L_*D_*DI_],  g_w2q_l[L_*D_*DI_];  __device__ float g_sw2[L_*D_];

// ---------------- small helpers ----------------
__device__ __forceinline__ float fast_ex2(float x) {
    float r; asm("ex2.approx.f32 %0, %1;" : "=f"(r) : "f"(x)); return r;
}
__device__ __forceinline__ float fast_rcp(float x) {
    float r; asm("rcp.approx.f32 %0, %1;" : "=f"(r) : "f"(x)); return r;
}
__device__ __forceinline__ float sigf(float x) {
    return fast_rcp(1.0f + fast_ex2(-1.4426950408889634f * x));
}
__device__ __forceinline__ float tanhf_(float x) {
    return fmaf(2.0f, sigf(2.0f * x), -1.0f);
}
__device__ __forceinline__ uint32_t s2u(const void* p) {
    uint32_t a; asm("{ .reg .u64 t; cvta.to.shared.u64 t, %1; cvt.u32.u64 %0, t; }"
                    : "=r"(a) : "l"(p)); return a;
}
__device__ __forceinline__ void cpasync16(uint32_t d, const void* s) {
    asm volatile("cp.async.ca.shared.global [%0], [%1], 16;" :: "r"(d), "l"(s));
}
__device__ __forceinline__ void cp_commit() {
    asm volatile("cp.async.commit_group;" ::: "memory");
}
__device__ __forceinline__ void ldm4(uint32_t* r, uint32_t addr) {
    asm volatile("ldmatrix.sync.aligned.m8n8.x4.shared.b16 {%0,%1,%2,%3}, [%4];"
                 : "=r"(r[0]), "=r"(r[1]), "=r"(r[2]), "=r"(r[3]) : "r"(addr));
}
// int8 MMA: D(s32) = A(s8,16x32) * B(s8,8x32)^T + C
__device__ __forceinline__ void mma16832(int* c, const uint32_t* a, const uint32_t* b) {
    asm volatile("mma.sync.aligned.m16n8k32.row.col.s32.s8.s8.s32 "
                 "{%0,%1,%2,%3}, {%4,%5,%6,%7}, {%8,%9}, {%0,%1,%2,%3};"
                 : "+r"(c[0]), "+r"(c[1]), "+r"(c[2]), "+r"(c[3])
                 : "r"(a[0]), "r"(a[1]), "r"(a[2]), "r"(a[3]), "r"(b[0]), "r"(b[1]));
}
// quantize one value pair helper: q = rint(v*inv); hi=(q+128)>>8; lo=q-256*hi
__device__ __forceinline__ void q8(float v, float inv, int8_t& h, int8_t& l) {
    const int q = __float2int_rn(v * inv);
    const int hi = (q + 128) >> 8;
    h = (int8_t)hi; l = (int8_t)(q - (hi << 8));
}

// ---------------- row quantize: fp32 [rows x ncols] -> int8 hi/lo + scale ------
__global__ void rowquant_kernel(const float* __restrict__ src,
                                int8_t* __restrict__ qh, int8_t* __restrict__ ql,
                                float* __restrict__ scale, int ncols)
{
    const int row = blockIdx.x, tid = threadIdx.x;
    const float* p = src + (size_t)row * ncols;
    float mx = 0.0f;
    for (int c = tid * 4; c < ncols; c += blockDim.x * 4) {
        const float4 v = *(const float4*)(p + c);
        mx = fmaxf(mx, fmaxf(fmaxf(fabsf(v.x), fabsf(v.y)),
                             fmaxf(fabsf(v.z), fabsf(v.w))));
    }
#pragma unroll
    for (int o = 16; o > 0; o >>= 1) mx = fmaxf(mx, __shfl_xor_sync(0xffffffffu, mx, o));
    __shared__ float wm[8];
    if ((tid & 31) == 0) wm[tid >> 5] = mx;
    __syncthreads();
    float rmax = 1e-30f;
    for (int i = 0; i < (int)(blockDim.x >> 5); i++) rmax = fmaxf(rmax, wm[i]);
    const float inv = 32256.0f / rmax;
    if (tid == 0) scale[row] = rmax / 32256.0f;
    for (int c = tid * 4; c < ncols; c += blockDim.x * 4) {
        const float4 v = *(const float4*)(p + c);
        int8_t h0,l0,h1,l1,h2,l2,h3,l3;
        q8(v.x, inv, h0, l0); q8(v.y, inv, h1, l1);
        q8(v.z, inv, h2, l2); q8(v.w, inv, h3, l3);
        *(char4*)(qh + (size_t)row * ncols + c) = make_char4(h0, h1, h2, h3);
        *(char4*)(ql + (size_t)row * ncols + c) = make_char4(l0, l1, l2, l3);
    }
}

// ---------------- layernorm -> int8 hi/lo + row scale ----------------
__global__ void __launch_bounds__(128) ln_kernel(
    const float* __restrict__ x, int8_t* __restrict__ qh, int8_t* __restrict__ ql,
    float* __restrict__ scale,
    const float* __restrict__ gw, const float* __restrict__ bw)
{
    const int row = blockIdx.x, t = threadIdx.x;
    const float4 v = *(const float4*)(x + (size_t)row * D_ + t * 4);
    float s  = v.x + v.y + v.z + v.w;
    float ss = v.x*v.x + v.y*v.y + v.z*v.z + v.w*v.w;
#pragma unroll
    for (int o = 16; o > 0; o >>= 1) {
        s  += __shfl_xor_sync(0xffffffffu, s,  o);
        ss += __shfl_xor_sync(0xffffffffu, ss, o);
    }
    __shared__ float rs[4], rss[4], rm[4];
    const int w = t >> 5, lane = t & 31;
    if (lane == 0) { rs[w] = s; rss[w] = ss; }
    __syncthreads();
    s  = rs[0] + rs[1] + rs[2] + rs[3];
    ss = rss[0] + rss[1] + rss[2] + rss[3];
    const float mean = s * (1.0f / D_);
    const float var  = ss * (1.0f / D_) - mean * mean;
    const float rstd = rsqrtf(var + 1e-6f);
    const float4 g4 = *(const float4*)(gw + t * 4);
    const float4 b4 = *(const float4*)(bw + t * 4);
    const float o0 = (v.x - mean) * rstd * g4.x + b4.x;
    const float o1 = (v.y - mean) * rstd * g4.y + b4.y;
    const float o2 = (v.z - mean) * rstd * g4.z + b4.z;
    const float o3 = (v.w - mean) * rstd * g4.w + b4.w;
    // row max for quantization
    float mx = fmaxf(fmaxf(fabsf(o0), fabsf(o1)), fmaxf(fabsf(o2), fabsf(o3)));
#pragma unroll
    for (int o = 16; o > 0; o >>= 1) mx = fmaxf(mx, __shfl_xor_sync(0xffffffffu, mx, o));
    if (lane == 0) rm[w] = mx;
    __syncthreads();
    const float rmax = fmaxf(fmaxf(fmaxf(rm[0], rm[1]), fmaxf(rm[2], rm[3])), 1e-30f);
    const float inv = 32256.0f / rmax;
    if (t == 0) scale[row] = rmax / 32256.0f;
    int8_t h0,l0,h1,l1,h2,l2,h3,l3;
    q8(o0, inv, h0, l0); q8(o1, inv, h1, l1);
    q8(o2, inv, h2, l2); q8(o3, inv, h3, l3);
    *(char4*)(qh + (size_t)row * D_ + t * 4) = make_char4(h0, h1, h2, h3);
    *(char4*)(ql + (size_t)row * D_ + t * 4) = make_char4(l0, l1, l2, l3);
}

// ---------------- final layernorm + projection ----------------
__global__ void __launch_bounds__(128) final_kernel(
    const float* __restrict__ x, const float* __restrict__ gw,
    const float* __restrict__ bw, const float* __restrict__ wp,
    float* __restrict__ out)
{
    const int row = blockIdx.x, t = threadIdx.x;
    const float4 v = *(const float4*)(x + (size_t)row * D_ + t * 4);
    float s  = v.x + v.y + v.z + v.w;
    float ss = v.x*v.x + v.y*v.y + v.z*v.z + v.w*v.w;
#pragma unroll
    for (int o = 16; o > 0; o >>= 1) {
        s  += __shfl_xor_sync(0xffffffffu, s,  o);
        ss += __shfl_xor_sync(0xffffffffu, ss, o);
    }
    __shared__ float rs[4], rss[4], rd[4];
    const int w = t >> 5, lane = t & 31;
    if (lane == 0) { rs[w] = s; rss[w] = ss; }
    __syncthreads();
    s  = rs[0] + rs[1] + rs[2] + rs[3];
    ss = rss[0] + rss[1] + rss[2] + rss[3];
    const float mean = s * (1.0f / D_);
    const float var  = ss * (1.0f / D_) - mean * mean;
    const float rstd = rsqrtf(var + 1e-6f);
    const float4 g4 = *(const float4*)(gw + t * 4);
    const float4 b4 = *(const float4*)(bw + t * 4);
    const float4 w4 = *(const float4*)(wp + t * 4);
    float d = ((v.x - mean) * rstd * g4.x + b4.x) * w4.x
            + ((v.y - mean) * rstd * g4.y + b4.y) * w4.y
            + ((v.z - mean) * rstd * g4.z + b4.z) * w4.z
            + ((v.w - mean) * rstd * g4.w + b4.w) * w4.w;
#pragma unroll
    for (int o = 16; o > 0; o >>= 1) d += __shfl_xor_sync(0xffffffffu, d, o);
    if (lane == 0) rd[w] = d;
    __syncthreads();
    if (t == 0) out[row] = rd[0] + rd[1] + rd[2] + rd[3];
}

// ======== int8 split GEMM: C = (sA sB) * [65536*Hh + 256*(Hl+Lh)] =============
// A,B int8 hi/lo, K-major (row stride KROW bytes). m16n8k32, int32 accum.
// cp.async 3-stage, 1 barrier/chunk, KC=64 int8 elements (64B rows).
#define SST  80   /* smem row stride bytes */

template<int TM, int TN, int NTHR,
         bool BIAS, bool RELU, bool RESID, bool APERM, bool CPERM, bool PART>
__global__ void __launch_bounds__(NTHR) qgemm(
    const int8_t* __restrict__ Ah, const int8_t* __restrict__ Al,
    const float* __restrict__ sA,
    const int8_t* __restrict__ Bh, const int8_t* __restrict__ Bl,
    const float* __restrict__ sB,
    const float* __restrict__ bias, const float* __restrict__ resid,
    float* __restrict__ C, int K, int KROW, int N)
{
    constexpr int WGN = NTHR / 64;
    constexpr int WM = TM / 2, WN = TN / WGN;
    constexpr int MFRAG = WM / 16, NFRAG = WN / 8;
    constexpr int AOFF_H = 0;
    constexpr int AOFF_L = TM * SST;
    constexpr int BOFF_H = 2 * TM * SST;
    constexpr int BOFF_L = 2 * TM * SST + TN * SST;
    constexpr int SSZ = 2 * (TM + TN) * SST;
    constexpr int RPI = NTHR / 4;      // rows loaded per iteration (64B per row)
    constexpr int AIT = (TM + RPI - 1) / RPI, BIT = (TN + RPI - 1) / RPI;

    extern __shared__ char smem[];
    const uint32_t sb = s2u(smem);
    const int tid = threadIdx.x;
    const int lane = tid & 31, warp = tid >> 5;
    const int m0 = blockIdx.y * TM, n0 = blockIdx.x * TN;
    const int wmo = (warp & 1) * WM, wno = (warp >> 1) * WN;
    const int k0 = PART ? blockIdx.z * K : 0;

    // ---- loader setup ----
    const int lrow = tid >> 2;
    const int lseg = (tid & 3) << 4;      // 0,16,32,48 byte within 64B chunk row
    const char* agh[AIT]; const char* agl[AIT]; uint32_t sa_[AIT];
    bool aok[AIT];
#pragma unroll
    for (int it = 0; it < AIT; it++) {
        const int r = lrow + it * RPI;
        aok[it] = (r < TM);
        const int rr = aok[it] ? r : 0;
        int am = m0 + rr;
        if (APERM) am = (am % S_) * B_ + am / S_;
        const size_t off = (size_t)am * KROW + k0 + lseg;
        agh[it] = (const char*)Ah + off;
        agl[it] = (const char*)Al + off;
        sa_[it] = (uint32_t)rr * SST + lseg;
    }
    const char* bgh[BIT]; const char* bgl[BIT]; uint32_t sbo[BIT];
    bool bok[BIT];
#pragma unroll
    for (int it = 0; it < BIT; it++) {
        const int r = lrow + it * RPI;
        bok[it] = (r < TN);
        const int rr = bok[it] ? r : 0;
        const size_t off = (size_t)(n0 + rr) * KROW + k0 + lseg;
        bgh[it] = (const char*)Bh + off;
        bgl[it] = (const char*)Bl + off;
        sbo[it] = (uint32_t)rr * SST + lseg;
    }

    auto load_chunk = [&](int chunk, uint32_t st) {
        const size_t ko = (size_t)chunk * 64;
#pragma unroll
        for (int it = 0; it < AIT; it++) {
            if (aok[it]) {
                cpasync16(st + AOFF_H + sa_[it], agh[it] + ko);
                cpasync16(st + AOFF_L + sa_[it], agl[it] + ko);
            }
        }
#pragma unroll
        for (int it = 0; it < BIT; it++) {
            if (bok[it]) {
                cpasync16(st + BOFF_H + sbo[it], bgh[it] + ko);
                cpasync16(st + BOFF_L + sbo[it], bgl[it] + ko);
            }
        }
    };

    int s1[MFRAG][NFRAG][4], s2[MFRAG][NFRAG][4];
#pragma unroll
    for (int i = 0; i < MFRAG; i++)
#pragma unroll
        for (int j = 0; j < NFRAG; j++)
#pragma unroll
            for (int q = 0; q < 4; q++) { s1[i][j][q] = 0; s2[i][j][q] = 0; }

    const int nc = K >> 6;   // K elements / 64

    load_chunk(0, sb);
    cp_commit();
    if (nc > 1) load_chunk(1, sb + SSZ);
    cp_commit();

    const uint32_t aRow = (uint32_t)(wmo + (lane & 15)) * SST + ((lane >> 4) << 4);
    const uint32_t bRow = (uint32_t)(wno + (lane & 7) + ((lane >> 4) & 1) * 8) * SST
                        + (((lane >> 3) & 1) << 4);

    for (int cc = 0; cc < nc; cc++) {
        asm volatile("cp.async.wait_group 1;" ::: "memory");
        __syncthreads();
        if (cc + 2 < nc) load_chunk(cc + 2, sb + ((cc + 2) % 3) * SSZ);
        cp_commit();

        const uint32_t st = sb + (cc % 3) * SSZ;
#pragma unroll
        for (int ks = 0; ks < 2; ks++) {
            const uint32_t kb = ks << 5;   // 0 or 32 bytes (K=32 int8 per mma)
            uint32_t a[MFRAG][4], al[MFRAG][4], bh[NFRAG][2], bl[NFRAG][2];
#pragma unroll
            for (int im = 0; im < MFRAG; im++)
                ldm4(a[im],  st + AOFF_H + aRow + (uint32_t)(im * 16) * SST + kb);
#pragma unroll
            for (int im = 0; im < MFRAG; im++)
                ldm4(al[im], st + AOFF_L + aRow + (uint32_t)(im * 16) * SST + kb);
#pragma unroll
            for (int nf2 = 0; nf2 < NFRAG / 2; nf2++) {
                uint32_t r[4];
                ldm4(r, st + BOFF_H + bRow + (uint32_t)(nf2 * 16) * SST + kb);
                bh[2*nf2][0] = r[0]; bh[2*nf2][1] = r[1];
                bh[2*nf2+1][0] = r[2]; bh[2*nf2+1][1] = r[3];
                ldm4(r, st + BOFF_L + bRow + (uint32_t)(nf2 * 16) * SST + kb);
                bl[2*nf2][0] = r[0]; bl[2*nf2][1] = r[1];
                bl[2*nf2+1][0] = r[2]; bl[2*nf2+1][1] = r[3];
            }
            // pass-major: hi*hi -> S1; hi*lo and lo*hi share S2 (equal weight 256)
#pragma unroll
            for (int im = 0; im < MFRAG; im++)
#pragma unroll
                for (int nf = 0; nf < NFRAG; nf++)
                    mma16832(s1[im][nf], a[im], bh[nf]);
#pragma unroll
            for (int im = 0; im < MFRAG; im++)
#pragma unroll
                for (int nf = 0; nf < NFRAG; nf++)
                    mma16832(s2[im][nf], a[im], bl[nf]);
#pragma unroll
            for (int im = 0; im < MFRAG; im++)
#pragma unroll
                for (int nf = 0; nf < NFRAG; nf++)
                    mma16832(s2[im][nf], al[im], bh[nf]);
        }
    }

    // ---- epilogue ----
    float* Cp = PART ? (C + (size_t)blockIdx.z * M_ * N) : C;
#pragma unroll
    for (int im = 0; im < MFRAG; im++) {
        const int rbase = m0 + wmo + im * 16 + (lane >> 2);
#pragma unroll
        for (int half = 0; half < 2; half++) {
            const int m = rbase + half * 8;
            const int am = APERM ? ((m % S_) * B_ + m / S_) : m;
            const int cm = CPERM ? ((m % S_) * B_ + m / S_) : m;
            const float sav = sA[am];
#pragma unroll
            for (int nf = 0; nf < NFRAG; nf++) {
                const int n = n0 + wno + nf * 8 + ((lane & 3) << 1);
                const float2 sb2 = *(const float2*)(sB + n);
                float v0 = sav * sb2.x * (65536.0f * (float)s1[im][nf][half*2]
                                          + 256.0f * (float)s2[im][nf][half*2]);
                float v1 = sav * sb2.y * (65536.0f * (float)s1[im][nf][half*2+1]
                                          + 256.0f * (float)s2[im][nf][half*2+1]);
                if (BIAS)  { const float2 bq = *(const float2*)(bias + n); v0 += bq.x; v1 += bq.y; }
                if (RELU)  { v0 = fmaxf(v0, 0.0f); v1 = fmaxf(v1, 0.0f); }
                if (RESID) { const float2 rq = *(const float2*)(resid + (size_t)m * N + n); v0 += rq.x; v1 += rq.y; }
                *(float2*)(Cp + (size_t)cm * N + n) = make_float2(v0, v1);
            }
        }
    }
}

// ---------------- w2 split-K reduce: x += b2 + sum_z part[z] ----------------
__global__ void __launch_bounds__(256) w2_reduce(
    const float* __restrict__ part, const float* __restrict__ bias,
    float* __restrict__ x)
{
    const int idx = blockIdx.x * 256 + threadIdx.x;   // over M_*D_/4
    const int n4 = idx & (D_ / 4 - 1);
    float4 acc = ((const float4*)x)[idx];
    const float4 b = ((const float4*)bias)[n4];
    acc.x += b.x; acc.y += b.y; acc.z += b.z; acc.w += b.w;
#pragma unroll
    for (int z = 0; z < SPLITK_W2; z++) {
        const float4 p = ((const float4*)(part + (size_t)z * M_ * D_))[idx];
        acc.x += p.x; acc.y += p.y; acc.z += p.z; acc.w += p.w;
    }
    ((float4*)x)[idx] = acc;
}

// ============ LSTM phase 1: identity run, checkpoint every step ==============
__global__ void __launch_bounds__(256) lstm_base(
    const float* __restrict__ gx, const float* __restrict__ whh,
    float* __restrict__ ckh, float* __restrict__ ckc, float* __restrict__ hf)
{
    const int b = blockIdx.x, tid = threadIdx.x;

    ull w[32];
    {
        const ulonglong2* wp = (const ulonglong2*)(whh + (size_t)tid * H_);
#pragma unroll
        for (int j = 0; j < 16; j++) {
            const ulonglong2 q = wp[j];
            w[2 * j] = q.x; w[2 * j + 1] = q.y;
        }
    }

    __shared__ __align__(16) float sh[H_];
    __shared__ float sgate[G4_];

    float c = 0.0f, hval = 0.0f;
    if (tid < H_) sh[tid] = 0.0f;
    __syncthreads();

    for (int t = 0; t < S_; t++) {
        if (tid < H_) {
            const size_t o = ((size_t)t * B_ + b) * H_ + tid;
            ckh[o] = hval; ckc[o] = c;
        }
        const float gxv = __ldg(gx + ((size_t)t * B_ + b) * G4_ + tid);
        {
            const ulonglong2* hp = (const ulonglong2*)sh;
            ull a0 = 0ull, a1 = 0ull;
#pragma unroll
            for (int j = 0; j < 16; j++) {
                const ulonglong2 q = hp[j];
                asm("fma.rn.f32x2 %0, %1, %2, %0;" : "+l"(a0) : "l"(w[2*j]),   "l"(q.x));
                asm("fma.rn.f32x2 %0, %1, %2, %0;" : "+l"(a1) : "l"(w[2*j+1]), "l"(q.y));
            }
            float p0x, p0y, p1x, p1y;
            asm("mov.b64 {%0, %1}, %2;" : "=f"(p0x), "=f"(p0y) : "l"(a0));
            asm("mov.b64 {%0, %1}, %2;" : "=f"(p1x), "=f"(p1y) : "l"(a1));
            sgate[tid] = gxv + (p0x + p0y) + (p1x + p1y);
        }
        __syncthreads();
        if (tid < H_) {
            const float iv = sgate[tid];
            const float fv = sgate[64 + tid];
            const float gv = sgate[128 + tid];
            const float ov = sgate[192 + tid];
            c    = sigf(fv) * c + sigf(iv) * tanhf_(gv);
            hval = sigf(ov) * tanhf_(c);
            sh[tid] = hval;
        }
        __syncthreads();
    }
    if (tid < H_)
        hf[((size_t)(S_ - 1) * B_ + b) * H_ + tid] = hval;
}

// ============ LSTM phase 2: resume from checkpoint i, steps i..79 =============
__global__ void __launch_bounds__(256) lstm_resume(
    const float* __restrict__ gx, const float* __restrict__ whh,
    const float* __restrict__ ckh, const float* __restrict__ ckc,
    float* __restrict__ hf)
{
    const int tid = threadIdx.x;
    const int i = blockIdx.x >> 2;
    const int g = blockIdx.x & 3;

    ull w[32];
    {
        const ulonglong2* wp = (const ulonglong2*)(whh + (size_t)tid * H_);
#pragma unroll
        for (int j = 0; j < 16; j++) {
            const ulonglong2 q = wp[j];
            w[2 * j] = q.x; w[2 * j + 1] = q.y;
        }
    }

    __shared__ __align__(16) float sh[NS][H_];
    __shared__ float sgate[NS][G4_];

    const int my_s = tid >> 6, my_k = tid & 63;
    const int my_b = g * NS + my_s;
    float c, hval;
    {
        const size_t o = ((size_t)i * B_ + my_b) * H_ + my_k;
        hval = ckh[o]; c = ckc[o];
        sh[my_s][my_k] = hval;
    }
    __syncthreads();

    for (int t = i; t < S_; t++) {
        const int src = (t == i) ? (S_ - 1) : ((t == S_ - 1) ? i : t);
        float gxv[NS];
#pragma unroll
        for (int s = 0; s < NS; s++)
            gxv[s] = __ldg(gx + ((size_t)src * B_ + g * NS + s) * G4_ + tid);
#pragma unroll
        for (int s = 0; s < NS; s++) {
            const ulonglong2* hp = (const ulonglong2*)sh[s];
            ull a0 = 0ull, a1 = 0ull;
#pragma unroll
            for (int j = 0; j < 16; j++) {
                const ulonglong2 q = hp[j];
                asm("fma.rn.f32x2 %0, %1, %2, %0;" : "+l"(a0) : "l"(w[2*j]),   "l"(q.x));
                asm("fma.rn.f32x2 %0, %1, %2, %0;" : "+l"(a1) : "l"(w[2*j+1]), "l"(q.y));
            }
            float p0x, p0y, p1x, p1y;
            asm("mov.b64 {%0, %1}, %2;" : "=f"(p0x), "=f"(p0y) : "l"(a0));
            asm("mov.b64 {%0, %1}, %2;" : "=f"(p1x), "=f"(p1y) : "l"(a1));
            sgate[s][tid] = gxv[s] + (p0x + p0y) + (p1x + p1y);
        }
        __syncthreads();
        const float iv = sgate[my_s][my_k];
        const float fv = sgate[my_s][64 + my_k];
        const float gv = sgate[my_s][128 + my_k];
        const float ov = sgate[my_s][192 + my_k];
        c    = sigf(fv) * c + sigf(iv) * tanhf_(gv);
        hval = sigf(ov) * tanhf_(c);
        sh[my_s][my_k] = hval;
        __syncthreads();
    }
    hf[((size_t)i * B_ + my_b) * H_ + my_k] = hval;
}

// ---------------- launch ----------------
#define SMEM_T(TM, TN) (3 * 2 * ((TM) + (TN)) * SST)

extern "C" void kernel_launch(void* const* d_in, const int* in_sizes, int n_in,
                              void* d_out, int out_size)
{
    const float* src  = (const float*)d_in[0];
    const float* ln1g = (const float*)d_in[2];
    const float* ln1b = (const float*)d_in[3];
    const float* wih  = (const float*)d_in[4];
    const float* whh  = (const float*)d_in[5];
    const float* wfc  = (const float*)d_in[6];
    const float* ln2g = (const float*)d_in[7];
    const float* ln2b = (const float*)d_in[8];
    const float* w1   = (const float*)d_in[9];
    const float* b1   = (const float*)d_in[10];
    const float* w2   = (const float*)d_in[11];
    const float* b2   = (const float*)d_in[12];
    const float* lnfg = (const float*)d_in[13];
    const float* lnfb = (const float*)d_in[14];
    const float* wprj = (const float*)d_in[15];
    float* out = (float*)d_out;

    float *px, *pxg, *py, *phf, *pckh, *pckc, *ppart;
    float *psxn, *pshq, *psy, *pswih, *pswfc, *psw1, *psw2;
    int8_t *pxnh, *pxnl, *phh, *phl, *pyh, *pyl;
    int8_t *pwihh, *pwihl, *pwfch, *pwfcl, *pw1h, *pw1l, *pw2h, *pw2l;
    cudaGetSymbolAddress((void**)&px,   g_x);
    cudaGetSymbolAddress((void**)&pxg,  g_xg);
    cudaGetSymbolAddress((void**)&py,   g_y);
    cudaGetSymbolAddress((void**)&phf,  g_hf);
    cudaGetSymbolAddress((void**)&pckh, g_ckh);  cudaGetSymbolAddress((void**)&pckc, g_ckc);
    cudaGetSymbolAddress((void**)&ppart, g_part);
    cudaGetSymbolAddress((void**)&pxnh, g_xnq_h); cudaGetSymbolAddress((void**)&pxnl, g_xnq_l);
    cudaGetSymbolAddress((void**)&phh,  g_hq_h);  cudaGetSymbolAddress((void**)&phl,  g_hq_l);
    cudaGetSymbolAddress((void**)&pyh,  g_yq_h);  cudaGetSymbolAddress((void**)&pyl,  g_yq_l);
    cudaGetSymbolAddress((void**)&psxn, g_sxn);   cudaGetSymbolAddress((void**)&pshq, g_shq);
    cudaGetSymbolAddress((void**)&psy,  g_sy);
    cudaGetSymbolAddress((void**)&pwihh, g_wihq_h); cudaGetSymbolAddress((void**)&pwihl, g_wihq_l);
    cudaGetSymbolAddress((void**)&pwfch, g_wfcq_h); cudaGetSymbolAddress((void**)&pwfcl, g_wfcq_l);
    cudaGetSymbolAddress((void**)&pw1h, g_w1q_h);   cudaGetSymbolAddress((void**)&pw1l, g_w1q_l);
    cudaGetSymbolAddress((void**)&pw2h, g_w2q_h);   cudaGetSymbolAddress((void**)&pw2l, g_w2q_l);
    cudaGetSymbolAddress((void**)&pswih, g_swih);   cudaGetSymbolAddress((void**)&pswfc, g_swfc);
    cudaGetSymbolAddress((void**)&psw1, g_sw1);     cudaGetSymbolAddress((void**)&psw2, g_sw2);

    auto kwih = qgemm<32, 32, 128, false, false, false, false, true,  false>;
    auto kfc  = qgemm<32, 64, 128, false, false, true,  true,  false, false>;
    auto kw1  = qgemm<64, 64, 128, true,  true,  false, false, false, false>;
    auto kw2  = qgemm<64, 64, 128, false, false, false, false, false, true >;

    cudaFuncSetAttribute(kwih, cudaFuncAttributeMaxDynamicSharedMemorySize, SMEM_T(32, 32));
    cudaFuncSetAttribute(kfc,  cudaFuncAttributeMaxDynamicSharedMemorySize, SMEM_T(32, 64));
    cudaFuncSetAttribute(kw1,  cudaFuncAttributeMaxDynamicSharedMemorySize, SMEM_T(64, 64));
    cudaFuncSetAttribute(kw2,  cudaFuncAttributeMaxDynamicSharedMemorySize, SMEM_T(64, 64));

    cudaMemcpyAsync(px, src, (size_t)M_ * D_ * sizeof(float),
                    cudaMemcpyDeviceToDevice, 0);

    // quantize all weights once per launch (per-row scales)
    rowquant_kernel<<<L_*G4_, 128>>>(wih, pwihh, pwihl, pswih, D_);
    rowquant_kernel<<<L_*D_,  128>>>(wfc, pwfch, pwfcl, pswfc, H_);
    rowquant_kernel<<<L_*DI_, 128>>>(w1,  pw1h,  pw1l,  psw1,  D_);
    rowquant_kernel<<<L_*D_,  256>>>(w2,  pw2h,  pw2l,  psw2,  DI_);

    for (int l = 0; l < L_; l++) {
        ln_kernel<<<M_, 128>>>(px, pxnh, pxnl, psxn, ln1g + l * D_, ln1b + l * D_);
        // xg[s,b,:] = xn @ wih^T  (CPERM) — grid 8x40 = 320
        kwih<<<dim3(G4_/32, M_/32), 128, SMEM_T(32, 32)>>>(
            pxnh, pxnl, psxn,
            pwihh + (size_t)l*G4_*D_, pwihl + (size_t)l*G4_*D_, pswih + l*G4_,
            nullptr, nullptr, pxg, D_, D_, G4_);
        // Janossy LSTM
        lstm_base<<<B_, 256>>>(pxg, whh + (size_t)l*G4_*H_, pckh, pckc, phf);
        lstm_resume<<<(S_-1)*(B_/NS), 256>>>(pxg, whh + (size_t)l*G4_*H_,
                                             pckh, pckc, phf);
        // quantize h rows (64 cols)
        rowquant_kernel<<<M_, 64>>>(phf, phh, phl, pshq, H_);
        // x += h @ wfc^T  (APERM + RESID) — grid 8x40 = 320
        kfc<<<dim3(D_/64, M_/32), 128, SMEM_T(32, 64)>>>(
            phh, phl, pshq,
            pwfch + (size_t)l*D_*H_, pwfcl + (size_t)l*D_*H_, pswfc + l*D_,
            nullptr, px, px, H_, H_, D_);
        ln_kernel<<<M_, 128>>>(px, pxnh, pxnl, psxn, ln2g + l * D_, ln2b + l * D_);
        // y = relu(xn @ w1^T + b1) fp32 — grid 32x20 = 640
        kw1<<<dim3(DI_/64, M_/64), 128, SMEM_T(64, 64)>>>(
            pxnh, pxnl, psxn,
            pw1h + (size_t)l*DI_*D_, pw1l + (size_t)l*DI_*D_, psw1 + l*DI_,
            b1 + l*DI_, nullptr, py, D_, D_, DI_);
        // quantize y rows (2048 cols)
        rowquant_kernel<<<M_, 256>>>(py, pyh, pyl, psy, DI_);
        // w2 split-K partials — grid 8x20x4 = 640
        kw2<<<dim3(D_/64, M_/64, SPLITK_W2), 128, SMEM_T(64, 64)>>>(
            pyh, pyl, psy,
            pw2h + (size_t)l*D_*DI_, pw2l + (size_t)l*D_*DI_, psw2 + l*D_,
            nullptr, nullptr, ppart, DI_/SPLITK_W2, DI_, D_);
        // x += b2 + sum_z part[z]
        w2_reduce<<<M_*D_/4/256, 256>>>(ppart, b2 + l*D_, px);
    }
    final_kernel<<<M_, 128>>>(px, lnfg, lnfb, wprj, out);
}

// round 14
// speedup vs baseline: 1.6464x; 1.6464x over previous
#include <cuda_runtime.h>
#include <cuda_fp16.h>
#include <cstdint>

#define B_  16
#define S_  80
#define D_  512
#define H_  64
#define G4_ 256    /* 4*H */
#define DI_ 2048
#define L_  6
#define M_  (B_*S_)   /* 1280 rows */
#define NS  4         /* samples per LSTM resume block */
#define SPLITK_W2 4

typedef unsigned long long ull;

// ---------------- scratch (static device globals; no allocation) ----------------
__device__ float  g_x [M_*D_];     // residual stream (fp32)
__device__ float  g_xg[M_*G4_];    // gate projections, layout [(s*16+b)*256+g]
__device__ float  g_ckh[S_*B_*H_], g_ckc[S_*B_*H_]; // LSTM checkpoints
__device__ float  g_part[SPLITK_W2*M_*D_];          // w2 split-K partials
__device__ __half g_xn[M_*D_];     // layernorm out (fp16)
__device__ __half g_yq[M_*DI_];    // FFN hidden (fp16)
__device__ __half g_hq[M_*H_];     // LSTM hidden (fp16)
__device__ __half g_wih16[L_*G4_*D_];
__device__ __half g_wfc16[L_*D_*H_];
__device__ __half g_w116[L_*DI_*D_];
__device__ __half g_w216[L_*D_*DI_];

// ---------------- small helpers ----------------
__device__ __forceinline__ float fast_ex2(float x) {
    float r; asm("ex2.approx.f32 %0, %1;" : "=f"(r) : "f"(x)); return r;
}
__device__ __forceinline__ float fast_rcp(float x) {
    float r; asm("rcp.approx.f32 %0, %1;" : "=f"(r) : "f"(x)); return r;
}
__device__ __forceinline__ float sigf(float x) {
    return fast_rcp(1.0f + fast_ex2(-1.4426950408889634f * x));
}
__device__ __forceinline__ float tanhf_(float x) {
    return fmaf(2.0f, sigf(2.0f * x), -1.0f);
}
__device__ __forceinline__ uint32_t s2u(const void* p) {
    uint32_t a; asm("{ .reg .u64 t; cvta.to.shared.u64 t, %1; cvt.u32.u64 %0, t; }"
                    : "=r"(a) : "l"(p)); return a;
}
__device__ __forceinline__ void cpasync16(uint32_t d, const void* s) {
    asm volatile("cp.async.ca.shared.global [%0], [%1], 16;" :: "r"(d), "l"(s));
}
__device__ __forceinline__ void cp_commit() {
    asm volatile("cp.async.commit_group;" ::: "memory");
}
// non-trans ldmatrix x4 — A (row-major [m][k]) and B ([n][k] = col-major operand)
__device__ __forceinline__ void ldm4(uint32_t* r, uint32_t addr) {
    asm volatile("ldmatrix.sync.aligned.m8n8.x4.shared.b16 {%0,%1,%2,%3}, [%4];"
                 : "=r"(r[0]), "=r"(r[1]), "=r"(r[2]), "=r"(r[3]) : "r"(addr));
}
__device__ __forceinline__ void mma16816(float* c, const uint32_t* a, const uint32_t* b) {
    asm volatile("mma.sync.aligned.m16n8k16.row.col.f32.f16.f16.f32 "
                 "{%0,%1,%2,%3}, {%4,%5,%6,%7}, {%8,%9}, {%0,%1,%2,%3};"
                 : "+f"(c[0]), "+f"(c[1]), "+f"(c[2]), "+f"(c[3])
                 : "r"(a[0]), "r"(a[1]), "r"(a[2]), "r"(a[3]), "r"(b[0]), "r"(b[1]));
}

// ---------------- fp32 -> fp16 convert kernel (weights, once per launch) ------
__global__ void __launch_bounds__(256) conv16_kernel(
    const float* __restrict__ src, __half* __restrict__ dst, int n4)
{
    const int i = blockIdx.x * blockDim.x + threadIdx.x;
    if (i >= n4) return;
    const float4 v = ((const float4*)src)[i];
    half2 a = __floats2half2_rn(v.x, v.y);
    half2 b = __floats2half2_rn(v.z, v.w);
    ((uint2*)dst)[i] = make_uint2(*(uint32_t*)&a, *(uint32_t*)&b);
}

// ---------------- layernorm -> fp16 ----------------
__global__ void __launch_bounds__(128) ln_kernel(
    const float* __restrict__ x, __half* __restrict__ y,
    const float* __restrict__ gw, const float* __restrict__ bw)
{
    const int row = blockIdx.x, t = threadIdx.x;
    const float4 v = *(const float4*)(x + (size_t)row * D_ + t * 4);
    float s  = v.x + v.y + v.z + v.w;
    float ss = v.x*v.x + v.y*v.y + v.z*v.z + v.w*v.w;
#pragma unroll
    for (int o = 16; o > 0; o >>= 1) {
        s  += __shfl_xor_sync(0xffffffffu, s,  o);
        ss += __shfl_xor_sync(0xffffffffu, ss, o);
    }
    __shared__ float rs[4], rss[4];
    const int w = t >> 5, lane = t & 31;
    if (lane == 0) { rs[w] = s; rss[w] = ss; }
    __syncthreads();
    s  = rs[0] + rs[1] + rs[2] + rs[3];
    ss = rss[0] + rss[1] + rss[2] + rss[3];
    const float mean = s * (1.0f / D_);
    const float var  = ss * (1.0f / D_) - mean * mean;
    const float rstd = rsqrtf(var + 1e-6f);
    const float4 g4 = *(const float4*)(gw + t * 4);
    const float4 b4 = *(const float4*)(bw + t * 4);
    half2 o01 = __floats2half2_rn((v.x - mean) * rstd * g4.x + b4.x,
                                  (v.y - mean) * rstd * g4.y + b4.y);
    half2 o23 = __floats2half2_rn((v.z - mean) * rstd * g4.z + b4.z,
                                  (v.w - mean) * rstd * g4.w + b4.w);
    *(uint2*)(y + (size_t)row * D_ + t * 4) =
        make_uint2(*(uint32_t*)&o01, *(uint32_t*)&o23);
}

// ---------------- final layernorm + projection ----------------
__global__ void __launch_bounds__(128) final_kernel(
    const float* __restrict__ x, const float* __restrict__ gw,
    const float* __restrict__ bw, const float* __restrict__ wp,
    float* __restrict__ out)
{
    const int row = blockIdx.x, t = threadIdx.x;
    const float4 v = *(const float4*)(x + (size_t)row * D_ + t * 4);
    float s  = v.x + v.y + v.z + v.w;
    float ss = v.x*v.x + v.y*v.y + v.z*v.z + v.w*v.w;
#pragma unroll
    for (int o = 16; o > 0; o >>= 1) {
        s  += __shfl_xor_sync(0xffffffffu, s,  o);
        ss += __shfl_xor_sync(0xffffffffu, ss, o);
    }
    __shared__ float rs[4], rss[4], rd[4];
    const int w = t >> 5, lane = t & 31;
    if (lane == 0) { rs[w] = s; rss[w] = ss; }
    __syncthreads();
    s  = rs[0] + rs[1] + rs[2] + rs[3];
    ss = rss[0] + rss[1] + rss[2] + rss[3];
    const float mean = s * (1.0f / D_);
    const float var  = ss * (1.0f / D_) - mean * mean;
    const float rstd = rsqrtf(var + 1e-6f);
    const float4 g4 = *(const float4*)(gw + t * 4);
    const float4 b4 = *(const float4*)(bw + t * 4);
    const float4 w4 = *(const float4*)(wp + t * 4);
    float d = ((v.x - mean) * rstd * g4.x + b4.x) * w4.x
            + ((v.y - mean) * rstd * g4.y + b4.y) * w4.y
            + ((v.z - mean) * rstd * g4.z + b4.z) * w4.z
            + ((v.w - mean) * rstd * g4.w + b4.w) * w4.w;
#pragma unroll
    for (int o = 16; o > 0; o >>= 1) d += __shfl_xor_sync(0xffffffffu, d, o);
    if (lane == 0) rd[w] = d;
    __syncthreads();
    if (t == 0) out[row] = rd[0] + rd[1] + rd[2] + rd[3];
}

// ========== fp16 GEMM: C = A(MxK) * B(NxK)^T, fp32 accum, single pass =========
// K-major, row stride KROW elements. cp.async 3-stage, 1 barrier per chunk.
// KC=32 fp16 elements = 64B rows. PART: split-K fp32 partials.
#define SST  80   /* smem row stride bytes: 80 mod 128 walks all 16B banks */

template<int TM, int TN, int NTHR,
         bool BIAS, bool RELU, bool RESID, bool APERM, bool CPERM, bool OUTH, bool PART>
__global__ void __launch_bounds__(NTHR) hgemm(
    const __half* __restrict__ A, const __half* __restrict__ Bm,
    const float* __restrict__ bias, const float* __restrict__ resid,
    float* __restrict__ C, __half* __restrict__ Ch,
    int K, int KROW, int N)
{
    constexpr int WGN = NTHR / 64;
    constexpr int WM = TM / 2, WN = TN / WGN;
    constexpr int MFRAG = WM / 16, NFRAG = WN / 8;
    constexpr int BOFF = TM * SST;
    constexpr int SSZ = (TM + TN) * SST;
    constexpr int RPI = NTHR / 4;
    constexpr int AIT = (TM + RPI - 1) / RPI, BIT = (TN + RPI - 1) / RPI;

    extern __shared__ char smem[];
    const uint32_t sb = s2u(smem);
    const int tid = threadIdx.x;
    const int lane = tid & 31, warp = tid >> 5;
    const int m0 = blockIdx.y * TM, n0 = blockIdx.x * TN;
    const int wmo = (warp & 1) * WM, wno = (warp >> 1) * WN;
    const int k0 = PART ? blockIdx.z * K : 0;

    // ---- loader setup ----
    const int lrow = tid >> 2;
    const int lseg = (tid & 3) << 4;      // 0,16,32,48 byte within 64B chunk row
    const char* ag[AIT]; uint32_t sa[AIT]; bool aok[AIT];
#pragma unroll
    for (int it = 0; it < AIT; it++) {
        const int r = lrow + it * RPI;
        aok[it] = (r < TM);
        const int rr = aok[it] ? r : 0;
        int am = m0 + rr;
        if (APERM) am = (am % S_) * B_ + am / S_;
        ag[it] = (const char*)A + ((size_t)am * KROW + k0) * 2 + lseg;
        sa[it] = (uint32_t)rr * SST + lseg;
    }
    const char* bg[BIT]; uint32_t sbo[BIT]; bool bok[BIT];
#pragma unroll
    for (int it = 0; it < BIT; it++) {
        const int r = lrow + it * RPI;
        bok[it] = (r < TN);
        const int rr = bok[it] ? r : 0;
        bg[it]  = (const char*)Bm + ((size_t)(n0 + rr) * KROW + k0) * 2 + lseg;
        sbo[it] = (uint32_t)rr * SST + lseg;
    }

    auto load_chunk = [&](int chunk, uint32_t st) {
        const size_t ko = (size_t)chunk * 64;
#pragma unroll
        for (int it = 0; it < AIT; it++)
            if (aok[it]) cpasync16(st + sa[it], ag[it] + ko);
#pragma unroll
        for (int it = 0; it < BIT; it++)
            if (bok[it]) cpasync16(st + BOFF + sbo[it], bg[it] + ko);
    };

    float c[MFRAG][NFRAG][4];
#pragma unroll
    for (int i = 0; i < MFRAG; i++)
#pragma unroll
        for (int j = 0; j < NFRAG; j++)
#pragma unroll
            for (int q = 0; q < 4; q++) c[i][j][q] = 0.0f;

    const int nc = K >> 5;   // K / 32

    load_chunk(0, sb);
    cp_commit();
    if (nc > 1) load_chunk(1, sb + SSZ);
    cp_commit();

    const uint32_t aRow = (uint32_t)(wmo + (lane & 15)) * SST + ((lane >> 4) << 4);
    const uint32_t bRow = (uint32_t)(wno + (lane & 7) + ((lane >> 4) & 1) * 8) * SST
                        + (((lane >> 3) & 1) << 4);

    for (int cc = 0; cc < nc; cc++) {
        asm volatile("cp.async.wait_group 1;" ::: "memory");
        __syncthreads();
        if (cc + 2 < nc) load_chunk(cc + 2, sb + ((cc + 2) % 3) * SSZ);
        cp_commit();

        const uint32_t st = sb + (cc % 3) * SSZ;
#pragma unroll
        for (int ks = 0; ks < 2; ks++) {
            const uint32_t kb = ks << 5;   // 0 or 32 bytes
            uint32_t a[MFRAG][4], b[NFRAG][2];
#pragma unroll
            for (int im = 0; im < MFRAG; im++)
                ldm4(a[im], st + aRow + (uint32_t)(im * 16) * SST + kb);
#pragma unroll
            for (int nf2 = 0; nf2 < NFRAG / 2; nf2++) {
                uint32_t r[4];
                ldm4(r, st + BOFF + bRow + (uint32_t)(nf2 * 16) * SST + kb);
                b[2*nf2][0] = r[0]; b[2*nf2][1] = r[1];
                b[2*nf2+1][0] = r[2]; b[2*nf2+1][1] = r[3];
            }
#pragma unroll
            for (int im = 0; im < MFRAG; im++)
#pragma unroll
                for (int nf = 0; nf < NFRAG; nf++)
                    mma16816(c[im][nf], a[im], b[nf]);
        }
    }

    // ---- epilogue ----
    float* Cp = PART ? (C + (size_t)blockIdx.z * M_ * N) : C;
#pragma unroll
    for (int im = 0; im < MFRAG; im++) {
        const int rbase = m0 + wmo + im * 16 + (lane >> 2);
#pragma unroll
        for (int half_ = 0; half_ < 2; half_++) {
            const int m = rbase + half_ * 8;
            const int cm = CPERM ? ((m % S_) * B_ + m / S_) : m;
#pragma unroll
            for (int nf = 0; nf < NFRAG; nf++) {
                const int n = n0 + wno + nf * 8 + ((lane & 3) << 1);
                float v0 = c[im][nf][half_ * 2];
                float v1 = c[im][nf][half_ * 2 + 1];
                if (BIAS)  { const float2 bq = *(const float2*)(bias + n); v0 += bq.x; v1 += bq.y; }
                if (RELU)  { v0 = fmaxf(v0, 0.0f); v1 = fmaxf(v1, 0.0f); }
                if (RESID) { const float2 rq = *(const float2*)(resid + (size_t)m * N + n); v0 += rq.x; v1 += rq.y; }
                if (OUTH) {
                    half2 hv = __floats2half2_rn(v0, v1);
                    *(uint32_t*)(Ch + (size_t)cm * N + n) = *(uint32_t*)&hv;
                } else {
                    *(float2*)(Cp + (size_t)cm * N + n) = make_float2(v0, v1);
                }
            }
        }
    }
}

// ---------------- w2 split-K reduce: x += b2 + sum_z part[z] ----------------
__global__ void __launch_bounds__(256) w2_reduce(
    const float* __restrict__ part, const float* __restrict__ bias,
    float* __restrict__ x)
{
    const int idx = blockIdx.x * 256 + threadIdx.x;   // over M_*D_/4
    const int n4 = idx & (D_ / 4 - 1);
    float4 acc = ((const float4*)x)[idx];
    const float4 b = ((const float4*)bias)[n4];
    acc.x += b.x; acc.y += b.y; acc.z += b.z; acc.w += b.w;
#pragma unroll
    for (int z = 0; z < SPLITK_W2; z++) {
        const float4 p = ((const float4*)(part + (size_t)z * M_ * D_))[idx];
        acc.x += p.x; acc.y += p.y; acc.z += p.z; acc.w += p.w;
    }
    ((float4*)x)[idx] = acc;
}

// ============ LSTM phase 1: identity run, checkpoint every step ==============
__global__ void __launch_bounds__(256) lstm_base(
    const float* __restrict__ gx, const float* __restrict__ whh,
    float* __restrict__ ckh, float* __restrict__ ckc, __half* __restrict__ hq)
{
    const int b = blockIdx.x, tid = threadIdx.x;

    ull w[32];
    {
        const ulonglong2* wp = (const ulonglong2*)(whh + (size_t)tid * H_);
#pragma unroll
        for (int j = 0; j < 16; j++) {
            const ulonglong2 q = wp[j];
            w[2 * j] = q.x; w[2 * j + 1] = q.y;
        }
    }

    __shared__ __align__(16) float sh[H_];
    __shared__ float sgate[G4_];

    float c = 0.0f, hval = 0.0f;
    if (tid < H_) sh[tid] = 0.0f;
    __syncthreads();

    for (int t = 0; t < S_; t++) {
        if (tid < H_) {
            const size_t o = ((size_t)t * B_ + b) * H_ + tid;
            ckh[o] = hval; ckc[o] = c;
        }
        const float gxv = __ldg(gx + ((size_t)t * B_ + b) * G4_ + tid);
        {
            const ulonglong2* hp = (const ulonglong2*)sh;
            ull a0 = 0ull, a1 = 0ull;
#pragma unroll
            for (int j = 0; j < 16; j++) {
                const ulonglong2 q = hp[j];
                asm("fma.rn.f32x2 %0, %1, %2, %0;" : "+l"(a0) : "l"(w[2*j]),   "l"(q.x));
                asm("fma.rn.f32x2 %0, %1, %2, %0;" : "+l"(a1) : "l"(w[2*j+1]), "l"(q.y));
            }
            float p0x, p0y, p1x, p1y;
            asm("mov.b64 {%0, %1}, %2;" : "=f"(p0x), "=f"(p0y) : "l"(a0));
            asm("mov.b64 {%0, %1}, %2;" : "=f"(p1x), "=f"(p1y) : "l"(a1));
            sgate[tid] = gxv + (p0x + p0y) + (p1x + p1y);
        }
        __syncthreads();
        if (tid < H_) {
            const float iv = sgate[tid];
            const float fv = sgate[64 + tid];
            const float gv = sgate[128 + tid];
            const float ov = sgate[192 + tid];
            c    = sigf(fv) * c + sigf(iv) * tanhf_(gv);
            hval = sigf(ov) * tanhf_(c);
            sh[tid] = hval;
        }
        __syncthreads();
    }
    if (tid < H_)
        hq[((size_t)(S_ - 1) * B_ + b) * H_ + tid] = __float2half_rn(hval);
}

// ============ LSTM phase 2: resume from checkpoint i, steps i..79 =============
__global__ void __launch_bounds__(256) lstm_resume(
    const float* __restrict__ gx, const float* __restrict__ whh,
    const float* __restrict__ ckh, const float* __restrict__ ckc,
    __half* __restrict__ hq)
{
    const int tid = threadIdx.x;
    const int i = blockIdx.x >> 2;
    const int g = blockIdx.x & 3;

    ull w[32];
    {
        const ulonglong2* wp = (const ulonglong2*)(whh + (size_t)tid * H_);
#pragma unroll
        for (int j = 0; j < 16; j++) {
            const ulonglong2 q = wp[j];
            w[2 * j] = q.x; w[2 * j + 1] = q.y;
        }
    }

    __shared__ __align__(16) float sh[NS][H_];
    __shared__ float sgate[NS][G4_];

    const int my_s = tid >> 6, my_k = tid & 63;
    const int my_b = g * NS + my_s;
    float c, hval;
    {
        const size_t o = ((size_t)i * B_ + my_b) * H_ + my_k;
        hval = ckh[o]; c = ckc[o];
        sh[my_s][my_k] = hval;
    }
    __syncthreads();

    for (int t = i; t < S_; t++) {
        const int src = (t == i) ? (S_ - 1) : ((t == S_ - 1) ? i : t);
        float gxv[NS];
#pragma unroll
        for (int s = 0; s < NS; s++)
            gxv[s] = __ldg(gx + ((size_t)src * B_ + g * NS + s) * G4_ + tid);
#pragma unroll
        for (int s = 0; s < NS; s++) {
            const ulonglong2* hp = (const ulonglong2*)sh[s];
            ull a0 = 0ull, a1 = 0ull;
#pragma unroll
            for (int j = 0; j < 16; j++) {
                const ulonglong2 q = hp[j];
                asm("fma.rn.f32x2 %0, %1, %2, %0;" : "+l"(a0) : "l"(w[2*j]),   "l"(q.x));
                asm("fma.rn.f32x2 %0, %1, %2, %0;" : "+l"(a1) : "l"(w[2*j+1]), "l"(q.y));
            }
            float p0x, p0y, p1x, p1y;
            asm("mov.b64 {%0, %1}, %2;" : "=f"(p0x), "=f"(p0y) : "l"(a0));
            asm("mov.b64 {%0, %1}, %2;" : "=f"(p1x), "=f"(p1y) : "l"(a1));
            sgate[s][tid] = gxv[s] + (p0x + p0y) + (p1x + p1y);
        }
        __syncthreads();
        const float iv = sgate[my_s][my_k];
        const float fv = sgate[my_s][64 + my_k];
        const float gv = sgate[my_s][128 + my_k];
        const float ov = sgate[my_s][192 + my_k];
        c    = sigf(fv) * c + sigf(iv) * tanhf_(gv);
        hval = sigf(ov) * tanhf_(c);
        sh[my_s][my_k] = hval;
        __syncthreads();
    }
    hq[((size_t)i * B_ + my_b) * H_ + my_k] = __float2half_rn(hval);
}

// ---------------- launch ----------------
#define SMEM_T(TM, TN) (3 * ((TM) + (TN)) * SST)

extern "C" void kernel_launch(void* const* d_in, const int* in_sizes, int n_in,
                              void* d_out, int out_size)
{
    const float* src  = (const float*)d_in[0];
    const float* ln1g = (const float*)d_in[2];
    const float* ln1b = (const float*)d_in[3];
    const float* wih  = (const float*)d_in[4];
    const float* whh  = (const float*)d_in[5];
    const float* wfc  = (const float*)d_in[6];
    const float* ln2g = (const float*)d_in[7];
    const float* ln2b = (const float*)d_in[8];
    const float* w1   = (const float*)d_in[9];
    const float* b1   = (const float*)d_in[10];
    const float* w2   = (const float*)d_in[11];
    const float* b2   = (const float*)d_in[12];
    const float* lnfg = (const float*)d_in[13];
    const float* lnfb = (const float*)d_in[14];
    const float* wprj = (const float*)d_in[15];
    float* out = (float*)d_out;

    float *px, *pxg, *pckh, *pckc, *ppart;
    __half *pxn, *pyq, *phq, *pwih16, *pwfc16, *pw116, *pw216;
    cudaGetSymbolAddress((void**)&px,   g_x);
    cudaGetSymbolAddress((void**)&pxg,  g_xg);
    cudaGetSymbolAddress((void**)&pckh, g_ckh);  cudaGetSymbolAddress((void**)&pckc, g_ckc);
    cudaGetSymbolAddress((void**)&ppart, g_part);
    cudaGetSymbolAddress((void**)&pxn,  g_xn);
    cudaGetSymbolAddress((void**)&pyq,  g_yq);
    cudaGetSymbolAddress((void**)&phq,  g_hq);
    cudaGetSymbolAddress((void**)&pwih16, g_wih16);
    cudaGetSymbolAddress((void**)&pwfc16, g_wfc16);
    cudaGetSymbolAddress((void**)&pw116,  g_w116);
    cudaGetSymbolAddress((void**)&pw216,  g_w216);

    // kernel aliases (tiles/grids identical to the R11 best)
    auto kwih = hgemm<32, 32, 128, false, false, false, false, true,  false, false>;
    auto kfc  = hgemm<64, 64, 128, false, false, true,  true,  false, false, false>;
    auto kw1  = hgemm<64, 128,128, true,  true,  false, false, false, true,  false>;
    auto kw2  = hgemm<64, 128,128, false, false, false, false, false, false, true >;

    cudaFuncSetAttribute(kwih, cudaFuncAttributeMaxDynamicSharedMemorySize, SMEM_T(32, 32));
    cudaFuncSetAttribute(kfc,  cudaFuncAttributeMaxDynamicSharedMemorySize, SMEM_T(64, 64));
    cudaFuncSetAttribute(kw1,  cudaFuncAttributeMaxDynamicSharedMemorySize, SMEM_T(64, 128));
    cudaFuncSetAttribute(kw2,  cudaFuncAttributeMaxDynamicSharedMemorySize, SMEM_T(64, 128));

    cudaMemcpyAsync(px, src, (size_t)M_ * D_ * sizeof(float),
                    cudaMemcpyDeviceToDevice, 0);

    // convert all weights to fp16 once
    conv16_kernel<<<(L_*G4_*D_/4 + 255)/256, 256>>>(wih, pwih16, L_*G4_*D_/4);
    conv16_kernel<<<(L_*D_*H_/4  + 255)/256, 256>>>(wfc, pwfc16, L_*D_*H_/4);
    conv16_kernel<<<(L_*DI_*D_/4 + 255)/256, 256>>>(w1,  pw116,  L_*DI_*D_/4);
    conv16_kernel<<<(L_*D_*DI_/4 + 255)/256, 256>>>(w2,  pw216,  L_*D_*DI_/4);

    for (int l = 0; l < L_; l++) {
        ln_kernel<<<M_, 128>>>(px, pxn, ln1g + l * D_, ln1b + l * D_);
        // xg[s,b,:] = xn @ wih^T  (CPERM) — grid 8x40 = 320
        kwih<<<dim3(G4_/32, M_/32), 128, SMEM_T(32, 32)>>>(
            pxn, pwih16 + (size_t)l*G4_*D_, nullptr, nullptr,
            pxg, nullptr, D_, D_, G4_);
        // Janossy LSTM
        lstm_base<<<B_, 256>>>(pxg, whh + (size_t)l*G4_*H_, pckh, pckc, phq);
        lstm_resume<<<(S_-1)*(B_/NS), 256>>>(pxg, whh + (size_t)l*G4_*H_,
                                             pckh, pckc, phq);
        // x += h @ wfc^T  (APERM + RESID) — grid 8x20 = 160
        kfc<<<dim3(D_/64, M_/64), 128, SMEM_T(64, 64)>>>(
            phq, pwfc16 + (size_t)l*D_*H_, nullptr, px,
            px, nullptr, H_, H_, D_);
        ln_kernel<<<M_, 128>>>(px, pxn, ln2g + l * D_, ln2b + l * D_);
        // y = relu(xn @ w1^T + b1) -> fp16 — grid 16x20 = 320
        kw1<<<dim3(DI_/128, M_/64), 128, SMEM_T(64, 128)>>>(
            pxn, pw116 + (size_t)l*DI_*D_, b1 + l*DI_, nullptr,
            nullptr, pyq, D_, D_, DI_);
        // w2 split-K partials — grid 4x20x4 = 320
        kw2<<<dim3(D_/128, M_/64, SPLITK_W2), 128, SMEM_T(64, 128)>>>(
            pyq, pw216 + (size_t)l*D_*DI_, nullptr, nullptr,
            ppart, nullptr, DI_/SPLITK_W2, DI_, D_);
        // x += b2 + sum_z part[z]
        w2_reduce<<<M_*D_/4/256, 256>>>(ppart, b2 + l*D_, px);
    }
    final_kernel<<<M_, 128>>>(px, lnfg, lnfb, wprj, out);
}

// round 15
// speedup vs baseline: 1.6951x; 1.0296x over previous
#include <cuda_runtime.h>
#include <cuda_fp16.h>
#include <cstdint>

#define B_  16
#define S_  80
#define D_  512
#define H_  64
#define G4_ 256    /* 4*H */
#define DI_ 2048
#define L_  6
#define M_  (B_*S_)   /* 1280 rows */
#define NS  4         /* samples per LSTM resume block */
#define SPLITK_W2 4

typedef unsigned long long ull;

// ---------------- scratch (static device globals; no allocation) ----------------
__device__ float  g_x [M_*D_];     // residual stream (fp32)
__device__ float  g_xg[M_*G4_];    // gate projections, layout [(s*16+b)*256+g]
__device__ float  g_ckh[S_*B_*H_], g_ckc[S_*B_*H_]; // LSTM checkpoints
__device__ float  g_part[SPLITK_W2*M_*D_];          // w2 split-K partials
__device__ __half g_xn[M_*D_];     // layernorm out (fp16)
__device__ __half g_yq[M_*DI_];    // FFN hidden (fp16)
__device__ __half g_hq[M_*H_];     // LSTM hidden (fp16)
__device__ __half g_wih16[L_*G4_*D_];
__device__ __half g_wfc16[L_*D_*H_];
__device__ __half g_w116[L_*DI_*D_];
__device__ __half g_w216[L_*D_*DI_];

// ---------------- small helpers ----------------
__device__ __forceinline__ float fast_ex2(float x) {
    float r; asm("ex2.approx.f32 %0, %1;" : "=f"(r) : "f"(x)); return r;
}
__device__ __forceinline__ float fast_rcp(float x) {
    float r; asm("rcp.approx.f32 %0, %1;" : "=f"(r) : "f"(x)); return r;
}
__device__ __forceinline__ float sigf(float x) {
    return fast_rcp(1.0f + fast_ex2(-1.4426950408889634f * x));
}
__device__ __forceinline__ float tanhf_(float x) {
    return fmaf(2.0f, sigf(2.0f * x), -1.0f);
}
__device__ __forceinline__ uint32_t s2u(const void* p) {
    uint32_t a; asm("{ .reg .u64 t; cvta.to.shared.u64 t, %1; cvt.u32.u64 %0, t; }"
                    : "=r"(a) : "l"(p)); return a;
}
__device__ __forceinline__ void cpasync16(uint32_t d, const void* s) {
    asm volatile("cp.async.ca.shared.global [%0], [%1], 16;" :: "r"(d), "l"(s));
}
__device__ __forceinline__ void cp_commit() {
    asm volatile("cp.async.commit_group;" ::: "memory");
}
// non-trans ldmatrix x4 — A (row-major [m][k]) and B ([n][k] = col-major operand)
__device__ __forceinline__ void ldm4(uint32_t* r, uint32_t addr) {
    asm volatile("ldmatrix.sync.aligned.m8n8.x4.shared.b16 {%0,%1,%2,%3}, [%4];"
                 : "=r"(r[0]), "=r"(r[1]), "=r"(r[2]), "=r"(r[3]) : "r"(addr));
}
__device__ __forceinline__ void mma16816(float* c, const uint32_t* a, const uint32_t* b) {
    asm volatile("mma.sync.aligned.m16n8k16.row.col.f32.f16.f16.f32 "
                 "{%0,%1,%2,%3}, {%4,%5,%6,%7}, {%8,%9}, {%0,%1,%2,%3};"
                 : "+f"(c[0]), "+f"(c[1]), "+f"(c[2]), "+f"(c[3])
                 : "r"(a[0]), "r"(a[1]), "r"(a[2]), "r"(a[3]), "r"(b[0]), "r"(b[1]));
}

// ---------------- fp32 -> fp16 convert kernel (weights, once per launch) ------
__global__ void __launch_bounds__(256) conv16_kernel(
    const float* __restrict__ src, __half* __restrict__ dst, int n4)
{
    const int i = blockIdx.x * blockDim.x + threadIdx.x;
    if (i >= n4) return;
    const float4 v = ((const float4*)src)[i];
    half2 a = __floats2half2_rn(v.x, v.y);
    half2 b = __floats2half2_rn(v.z, v.w);
    ((uint2*)dst)[i] = make_uint2(*(uint32_t*)&a, *(uint32_t*)&b);
}

// ---------------- layernorm -> fp16 ----------------
__global__ void __launch_bounds__(128) ln_kernel(
    const float* __restrict__ x, __half* __restrict__ y,
    const float* __restrict__ gw, const float* __restrict__ bw)
{
    const int row = blockIdx.x, t = threadIdx.x;
    const float4 v = *(const float4*)(x + (size_t)row * D_ + t * 4);
    float s  = v.x + v.y + v.z + v.w;
    float ss = v.x*v.x + v.y*v.y + v.z*v.z + v.w*v.w;
#pragma unroll
    for (int o = 16; o > 0; o >>= 1) {
        s  += __shfl_xor_sync(0xffffffffu, s,  o);
        ss += __shfl_xor_sync(0xffffffffu, ss, o);
    }
    __shared__ float rs[4], rss[4];
    const int w = t >> 5, lane = t & 31;
    if (lane == 0) { rs[w] = s; rss[w] = ss; }
    __syncthreads();
    s  = rs[0] + rs[1] + rs[2] + rs[3];
    ss = rss[0] + rss[1] + rss[2] + rss[3];
    const float mean = s * (1.0f / D_);
    const float var  = ss * (1.0f / D_) - mean * mean;
    const float rstd = rsqrtf(var + 1e-6f);
    const float4 g4 = *(const float4*)(gw + t * 4);
    const float4 b4 = *(const float4*)(bw + t * 4);
    half2 o01 = __floats2half2_rn((v.x - mean) * rstd * g4.x + b4.x,
                                  (v.y - mean) * rstd * g4.y + b4.y);
    half2 o23 = __floats2half2_rn((v.z - mean) * rstd * g4.z + b4.z,
                                  (v.w - mean) * rstd * g4.w + b4.w);
    *(uint2*)(y + (size_t)row * D_ + t * 4) =
        make_uint2(*(uint32_t*)&o01, *(uint32_t*)&o23);
}

// ---------------- final layernorm + projection ----------------
__global__ void __launch_bounds__(128) final_kernel(
    const float* __restrict__ x, const float* __restrict__ gw,
    const float* __restrict__ bw, const float* __restrict__ wp,
    float* __restrict__ out)
{
    const int row = blockIdx.x, t = threadIdx.x;
    const float4 v = *(const float4*)(x + (size_t)row * D_ + t * 4);
    float s  = v.x + v.y + v.z + v.w;
    float ss = v.x*v.x + v.y*v.y + v.z*v.z + v.w*v.w;
#pragma unroll
    for (int o = 16; o > 0; o >>= 1) {
        s  += __shfl_xor_sync(0xffffffffu, s,  o);
        ss += __shfl_xor_sync(0xffffffffu, ss, o);
    }
    __shared__ float rs[4], rss[4], rd[4];
    const int w = t >> 5, lane = t & 31;
    if (lane == 0) { rs[w] = s; rss[w] = ss; }
    __syncthreads();
    s  = rs[0] + rs[1] + rs[2] + rs[3];
    ss = rss[0] + rss[1] + rss[2] + rss[3];
    const float mean = s * (1.0f / D_);
    const float var  = ss * (1.0f / D_) - mean * mean;
    const float rstd = rsqrtf(var + 1e-6f);
    const float4 g4 = *(const float4*)(gw + t * 4);
    const float4 b4 = *(const float4*)(bw + t * 4);
    const float4 w4 = *(const float4*)(wp + t * 4);
    float d = ((v.x - mean) * rstd * g4.x + b4.x) * w4.x
            + ((v.y - mean) * rstd * g4.y + b4.y) * w4.y
            + ((v.z - mean) * rstd * g4.z + b4.z) * w4.z
            + ((v.w - mean) * rstd * g4.w + b4.w) * w4.w;
#pragma unroll
    for (int o = 16; o > 0; o >>= 1) d += __shfl_xor_sync(0xffffffffu, d, o);
    if (lane == 0) rd[w] = d;
    __syncthreads();
    if (t == 0) out[row] = rd[0] + rd[1] + rd[2] + rd[3];
}

// ========== fp16 GEMM: C = A(MxK) * B(NxK)^T, fp32 accum, single pass =========
// K-major, row stride KROW elements. cp.async 3-stage, 1 barrier per chunk.
// KC=64 fp16 elements = 128B rows (4 k-steps per chunk -> half the barriers).
#define SST  144   /* smem row stride bytes: 144 = 9 x 16B -> 8 rows walk 8 banks */

template<int TM, int TN, int NTHR,
         bool BIAS, bool RELU, bool RESID, bool APERM, bool CPERM, bool OUTH, bool PART>
__global__ void __launch_bounds__(NTHR) hgemm(
    const __half* __restrict__ A, const __half* __restrict__ Bm,
    const float* __restrict__ bias, const float* __restrict__ resid,
    float* __restrict__ C, __half* __restrict__ Ch,
    int K, int KROW, int N)
{
    constexpr int WGN = NTHR / 64;
    constexpr int WM = TM / 2, WN = TN / WGN;
    constexpr int MFRAG = WM / 16, NFRAG = WN / 8;
    constexpr int BOFF = TM * SST;
    constexpr int SSZ = (TM + TN) * SST;
    constexpr int RPI = NTHR / 8;      // rows loaded per iteration (8 thr x 16B = 128B row)
    constexpr int AIT = (TM + RPI - 1) / RPI, BIT = (TN + RPI - 1) / RPI;

    extern __shared__ char smem[];
    const uint32_t sb = s2u(smem);
    const int tid = threadIdx.x;
    const int lane = tid & 31, warp = tid >> 5;
    const int m0 = blockIdx.y * TM, n0 = blockIdx.x * TN;
    const int wmo = (warp & 1) * WM, wno = (warp >> 1) * WN;
    const int k0 = PART ? blockIdx.z * K : 0;

    // ---- loader setup ----
    const int lrow = tid >> 3;
    const int lseg = (tid & 7) << 4;      // 0..112 byte within 128B chunk row
    const char* ag[AIT]; uint32_t sa[AIT]; bool aok[AIT];
#pragma unroll
    for (int it = 0; it < AIT; it++) {
        const int r = lrow + it * RPI;
        aok[it] = (r < TM);
        const int rr = aok[it] ? r : 0;
        int am = m0 + rr;
        if (APERM) am = (am % S_) * B_ + am / S_;
        ag[it] = (const char*)A + ((size_t)am * KROW + k0) * 2 + lseg;
        sa[it] = (uint32_t)rr * SST + lseg;
    }
    const char* bg[BIT]; uint32_t sbo[BIT]; bool bok[BIT];
#pragma unroll
    for (int it = 0; it < BIT; it++) {
        const int r = lrow + it * RPI;
        bok[it] = (r < TN);
        const int rr = bok[it] ? r : 0;
        bg[it]  = (const char*)Bm + ((size_t)(n0 + rr) * KROW + k0) * 2 + lseg;
        sbo[it] = (uint32_t)rr * SST + lseg;
    }

    auto load_chunk = [&](int chunk, uint32_t st) {
        const size_t ko = (size_t)chunk * 128;
#pragma unroll
        for (int it = 0; it < AIT; it++)
            if (aok[it]) cpasync16(st + sa[it], ag[it] + ko);
#pragma unroll
        for (int it = 0; it < BIT; it++)
            if (bok[it]) cpasync16(st + BOFF + sbo[it], bg[it] + ko);
    };

    float c[MFRAG][NFRAG][4];
#pragma unroll
    for (int i = 0; i < MFRAG; i++)
#pragma unroll
        for (int j = 0; j < NFRAG; j++)
#pragma unroll
            for (int q = 0; q < 4; q++) c[i][j][q] = 0.0f;

    const int nc = K >> 6;   // K / 64

    load_chunk(0, sb);
    cp_commit();
    if (nc > 1) load_chunk(1, sb + SSZ);
    cp_commit();

    const uint32_t aRow = (uint32_t)(wmo + (lane & 15)) * SST + ((lane >> 4) << 4);
    const uint32_t bRow = (uint32_t)(wno + (lane & 7) + ((lane >> 4) & 1) * 8) * SST
                        + (((lane >> 3) & 1) << 4);

    for (int cc = 0; cc < nc; cc++) {
        asm volatile("cp.async.wait_group 1;" ::: "memory");
        __syncthreads();
        if (cc + 2 < nc) load_chunk(cc + 2, sb + ((cc + 2) % 3) * SSZ);
        cp_commit();

        const uint32_t st = sb + (cc % 3) * SSZ;
#pragma unroll
        for (int ks = 0; ks < 4; ks++) {          // 4 k-steps per 128B chunk
            const uint32_t kb = ks << 5;           // 0,32,64,96 bytes
            uint32_t a[MFRAG][4], b[NFRAG][2];
#pragma unroll
            for (int im = 0; im < MFRAG; im++)
                ldm4(a[im], st + aRow + (uint32_t)(im * 16) * SST + kb);
#pragma unroll
            for (int nf2 = 0; nf2 < NFRAG / 2; nf2++) {
                uint32_t r[4];
                ldm4(r, st + BOFF + bRow + (uint32_t)(nf2 * 16) * SST + kb);
                b[2*nf2][0] = r[0]; b[2*nf2][1] = r[1];
                b[2*nf2+1][0] = r[2]; b[2*nf2+1][1] = r[3];
            }
#pragma unroll
            for (int im = 0; im < MFRAG; im++)
#pragma unroll
                for (int nf = 0; nf < NFRAG; nf++)
                    mma16816(c[im][nf], a[im], b[nf]);
        }
    }

    // ---- epilogue ----
    float* Cp = PART ? (C + (size_t)blockIdx.z * M_ * N) : C;
#pragma unroll
    for (int im = 0; im < MFRAG; im++) {
        const int rbase = m0 + wmo + im * 16 + (lane >> 2);
#pragma unroll
        for (int half_ = 0; half_ < 2; half_++) {
            const int m = rbase + half_ * 8;
            const int cm = CPERM ? ((m % S_) * B_ + m / S_) : m;
#pragma unroll
            for (int nf = 0; nf < NFRAG; nf++) {
                const int n = n0 + wno + nf * 8 + ((lane & 3) << 1);
                float v0 = c[im][nf][half_ * 2];
                float v1 = c[im][nf][half_ * 2 + 1];
                if (BIAS)  { const float2 bq = *(const float2*)(bias + n); v0 += bq.x; v1 += bq.y; }
                if (RELU)  { v0 = fmaxf(v0, 0.0f); v1 = fmaxf(v1, 0.0f); }
                if (RESID) { const float2 rq = *(const float2*)(resid + (size_t)m * N + n); v0 += rq.x; v1 += rq.y; }
                if (OUTH) {
                    half2 hv = __floats2half2_rn(v0, v1);
                    *(uint32_t*)(Ch + (size_t)cm * N + n) = *(uint32_t*)&hv;
                } else {
                    *(float2*)(Cp + (size_t)cm * N + n) = make_float2(v0, v1);
                }
            }
        }
    }
}

// ---------------- w2 split-K reduce: x += b2 + sum_z part[z] ----------------
__global__ void __launch_bounds__(256) w2_reduce(
    const float* __restrict__ part, const float* __restrict__ bias,
    float* __restrict__ x)
{
    const int idx = blockIdx.x * 256 + threadIdx.x;   // over M_*D_/4
    const int n4 = idx & (D_ / 4 - 1);
    float4 acc = ((const float4*)x)[idx];
    const float4 b = ((const float4*)bias)[n4];
    acc.x += b.x; acc.y += b.y; acc.z += b.z; acc.w += b.w;
#pragma unroll
    for (int z = 0; z < SPLITK_W2; z++) {
        const float4 p = ((const float4*)(part + (size_t)z * M_ * D_))[idx];
        acc.x += p.x; acc.y += p.y; acc.z += p.z; acc.w += p.w;
    }
    ((float4*)x)[idx] = acc;
}

// ============ LSTM phase 1: identity run, checkpoint every step ==============
__global__ void __launch_bounds__(256) lstm_base(
    const float* __restrict__ gx, const float* __restrict__ whh,
    float* __restrict__ ckh, float* __restrict__ ckc, __half* __restrict__ hq)
{
    const int b = blockIdx.x, tid = threadIdx.x;

    ull w[32];
    {
        const ulonglong2* wp = (const ulonglong2*)(whh + (size_t)tid * H_);
#pragma unroll
        for (int j = 0; j < 16; j++) {
            const ulonglong2 q = wp[j];
            w[2 * j] = q.x; w[2 * j + 1] = q.y;
        }
    }

    __shared__ __align__(16) float sh[H_];
    __shared__ float sgate[G4_];

    float c = 0.0f, hval = 0.0f;
    if (tid < H_) sh[tid] = 0.0f;
    __syncthreads();

    for (int t = 0; t < S_; t++) {
        if (tid < H_) {
            const size_t o = ((size_t)t * B_ + b) * H_ + tid;
            ckh[o] = hval; ckc[o] = c;
        }
        const float gxv = __ldg(gx + ((size_t)t * B_ + b) * G4_ + tid);
        {
            const ulonglong2* hp = (const ulonglong2*)sh;
            ull a0 = 0ull, a1 = 0ull;
#pragma unroll
            for (int j = 0; j < 16; j++) {
                const ulonglong2 q = hp[j];
                asm("fma.rn.f32x2 %0, %1, %2, %0;" : "+l"(a0) : "l"(w[2*j]),   "l"(q.x));
                asm("fma.rn.f32x2 %0, %1, %2, %0;" : "+l"(a1) : "l"(w[2*j+1]), "l"(q.y));
            }
            float p0x, p0y, p1x, p1y;
            asm("mov.b64 {%0, %1}, %2;" : "=f"(p0x), "=f"(p0y) : "l"(a0));
            asm("mov.b64 {%0, %1}, %2;" : "=f"(p1x), "=f"(p1y) : "l"(a1));
            sgate[tid] = gxv + (p0x + p0y) + (p1x + p1y);
        }
        __syncthreads();
        if (tid < H_) {
            const float iv = sgate[tid];
            const float fv = sgate[64 + tid];
            const float gv = sgate[128 + tid];
            const float ov = sgate[192 + tid];
            c    = sigf(fv) * c + sigf(iv) * tanhf_(gv);
            hval = sigf(ov) * tanhf_(c);
            sh[tid] = hval;
        }
        __syncthreads();
    }
    if (tid < H_)
        hq[((size_t)(S_ - 1) * B_ + b) * H_ + tid] = __float2half_rn(hval);
}

// ============ LSTM phase 2: resume from checkpoint i, steps i..79 =============
__global__ void __launch_bounds__(256) lstm_resume(
    const float* __restrict__ gx, const float* __restrict__ whh,
    const float* __restrict__ ckh, const float* __restrict__ ckc,
    __half* __restrict__ hq)
{
    const int tid = threadIdx.x;
    const int i = blockIdx.x >> 2;
    const int g = blockIdx.x & 3;

    ull w[32];
    {
        const ulonglong2* wp = (const ulonglong2*)(whh + (size_t)tid * H_);
#pragma unroll
        for (int j = 0; j < 16; j++) {
            const ulonglong2 q = wp[j];
            w[2 * j] = q.x; w[2 * j + 1] = q.y;
        }
    }

    __shared__ __align__(16) float sh[NS][H_];
    __shared__ float sgate[NS][G4_];

    const int my_s = tid >> 6, my_k = tid & 63;
    const int my_b = g * NS + my_s;
    float c, hval;
    {
        const size_t o = ((size_t)i * B_ + my_b) * H_ + my_k;
        hval = ckh[o]; c = ckc[o];
        sh[my_s][my_k] = hval;
    }
    __syncthreads();

    for (int t = i; t < S_; t++) {
        const int src = (t == i) ? (S_ - 1) : ((t == S_ - 1) ? i : t);
        float gxv[NS];
#pragma unroll
        for (int s = 0; s < NS; s++)
            gxv[s] = __ldg(gx + ((size_t)src * B_ + g * NS + s) * G4_ + tid);
#pragma unroll
        for (int s = 0; s < NS; s++) {
            const ulonglong2* hp = (const ulonglong2*)sh[s];
            ull a0 = 0ull, a1 = 0ull;
#pragma unroll
            for (int j = 0; j < 16; j++) {
                const ulonglong2 q = hp[j];
                asm("fma.rn.f32x2 %0, %1, %2, %0;" : "+l"(a0) : "l"(w[2*j]),   "l"(q.x));
                asm("fma.rn.f32x2 %0, %1, %2, %0;" : "+l"(a1) : "l"(w[2*j+1]), "l"(q.y));
            }
            float p0x, p0y, p1x, p1y;
            asm("mov.b64 {%0, %1}, %2;" : "=f"(p0x), "=f"(p0y) : "l"(a0));
            asm("mov.b64 {%0, %1}, %2;" : "=f"(p1x), "=f"(p1y) : "l"(a1));
            sgate[s][tid] = gxv[s] + (p0x + p0y) + (p1x + p1y);
        }
        __syncthreads();
        const float iv = sgate[my_s][my_k];
        const float fv = sgate[my_s][64 + my_k];
        const float gv = sgate[my_s][128 + my_k];
        const float ov = sgate[my_s][192 + my_k];
        c    = sigf(fv) * c + sigf(iv) * tanhf_(gv);
        hval = sigf(ov) * tanhf_(c);
        sh[my_s][my_k] = hval;
        __syncthreads();
    }
    hq[((size_t)i * B_ + my_b) * H_ + my_k] = __float2half_rn(hval);
}

// ---------------- launch ----------------
#define SMEM_T(TM, TN) (3 * ((TM) + (TN)) * SST)

extern "C" void kernel_launch(void* const* d_in, const int* in_sizes, int n_in,
                              void* d_out, int out_size)
{
    const float* src  = (const float*)d_in[0];
    const float* ln1g = (const float*)d_in[2];
    const float* ln1b = (const float*)d_in[3];
    const float* wih  = (const float*)d_in[4];
    const float* whh  = (const float*)d_in[5];
    const float* wfc  = (const float*)d_in[6];
    const float* ln2g = (const float*)d_in[7];
    const float* ln2b = (const float*)d_in[8];
    const float* w1   = (const float*)d_in[9];
    const float* b1   = (const float*)d_in[10];
    const float* w2   = (const float*)d_in[11];
    const float* b2   = (const float*)d_in[12];
    const float* lnfg = (const float*)d_in[13];
    const float* lnfb = (const float*)d_in[14];
    const float* wprj = (const float*)d_in[15];
    float* out = (float*)d_out;

    float *px, *pxg, *pckh, *pckc, *ppart;
    __half *pxn, *pyq, *phq, *pwih16, *pwfc16, *pw116, *pw216;
    cudaGetSymbolAddress((void**)&px,   g_x);
    cudaGetSymbolAddress((void**)&pxg,  g_xg);
    cudaGetSymbolAddress((void**)&pckh, g_ckh);  cudaGetSymbolAddress((void**)&pckc, g_ckc);
    cudaGetSymbolAddress((void**)&ppart, g_part);
    cudaGetSymbolAddress((void**)&pxn,  g_xn);
    cudaGetSymbolAddress((void**)&pyq,  g_yq);
    cudaGetSymbolAddress((void**)&phq,  g_hq);
    cudaGetSymbolAddress((void**)&pwih16, g_wih16);
    cudaGetSymbolAddress((void**)&pwfc16, g_wfc16);
    cudaGetSymbolAddress((void**)&pw116,  g_w116);
    cudaGetSymbolAddress((void**)&pw216,  g_w216);

    // kernel aliases (tiles/grids identical to R14 best; KC=64)
    auto kwih = hgemm<32, 32, 128, false, false, false, false, true,  false, false>;
    auto kfc  = hgemm<64, 64, 128, false, false, true,  true,  false, false, false>;
    auto kw1  = hgemm<64, 128,128, true,  true,  false, false, false, true,  false>;
    auto kw2  = hgemm<64, 128,128, false, false, false, false, false, false, true >;

    cudaFuncSetAttribute(kwih, cudaFuncAttributeMaxDynamicSharedMemorySize, SMEM_T(32, 32));
    cudaFuncSetAttribute(kfc,  cudaFuncAttributeMaxDynamicSharedMemorySize, SMEM_T(64, 64));
    cudaFuncSetAttribute(kw1,  cudaFuncAttributeMaxDynamicSharedMemorySize, SMEM_T(64, 128));
    cudaFuncSetAttribute(kw2,  cudaFuncAttributeMaxDynamicSharedMemorySize, SMEM_T(64, 128));

    cudaMemcpyAsync(px, src, (size_t)M_ * D_ * sizeof(float),
                    cudaMemcpyDeviceToDevice, 0);

    // convert all weights to fp16 once
    conv16_kernel<<<(L_*G4_*D_/4 + 255)/256, 256>>>(wih, pwih16, L_*G4_*D_/4);
    conv16_kernel<<<(L_*D_*H_/4  + 255)/256, 256>>>(wfc, pwfc16, L_*D_*H_/4);
    conv16_kernel<<<(L_*DI_*D_/4 + 255)/256, 256>>>(w1,  pw116,  L_*DI_*D_/4);
    conv16_kernel<<<(L_*D_*DI_/4 + 255)/256, 256>>>(w2,  pw216,  L_*D_*DI_/4);

    for (int l = 0; l < L_; l++) {
        ln_kernel<<<M_, 128>>>(px, pxn, ln1g + l * D_, ln1b + l * D_);
        // xg[s,b,:] = xn @ wih^T  (CPERM) — grid 8x40 = 320, nc=8
        kwih<<<dim3(G4_/32, M_/32), 128, SMEM_T(32, 32)>>>(
            pxn, pwih16 + (size_t)l*G4_*D_, nullptr, nullptr,
            pxg, nullptr, D_, D_, G4_);
        // Janossy LSTM
        lstm_base<<<B_, 256>>>(pxg, whh + (size_t)l*G4_*H_, pckh, pckc, phq);
        lstm_resume<<<(S_-1)*(B_/NS), 256>>>(pxg, whh + (size_t)l*G4_*H_,
                                             pckh, pckc, phq);
        // x += h @ wfc^T  (APERM + RESID) — grid 8x20 = 160, nc=1
        kfc<<<dim3(D_/64, M_/64), 128, SMEM_T(64, 64)>>>(
            phq, pwfc16 + (size_t)l*D_*H_, nullptr, px,
            px, nullptr, H_, H_, D_);
        ln_kernel<<<M_, 128>>>(px, pxn, ln2g + l * D_, ln2b + l * D_);
        // y = relu(xn @ w1^T + b1) -> fp16 — grid 16x20 = 320, nc=8
        kw1<<<dim3(DI_/128, M_/64), 128, SMEM_T(64, 128)>>>(
            pxn, pw116 + (size_t)l*DI_*D_, b1 + l*DI_, nullptr,
            nullptr, pyq, D_, D_, DI_);
        // w2 split-K partials — grid 4x20x4 = 320, nc=8 per slice
        kw2<<<dim3(D_/128, M_/64, SPLITK_W2), 128, SMEM_T(64, 128)>>>(
            pyq, pw216 + (size_t)l*D_*DI_, nullptr, nullptr,
            ppart, nullptr, DI_/SPLITK_W2, DI_, D_);
        // x += b2 + sum_z part[z]
        w2_reduce<<<M_*D_/4/256, 256>>>(ppart, b2 + l*D_, px);
    }
    final_kernel<<<M_, 128>>>(px, lnfg, lnfb, wprj, out);
}

// round 16
// speedup vs baseline: 1.7464x; 1.0302x over previous
#include <cuda_runtime.h>
#include <cuda_fp16.h>
#include <cstdint>

#define B_  16
#define S_  80
#define D_  512
#define H_  64
#define G4_ 256    /* 4*H */
#define DI_ 2048
#define L_  6
#define M_  (B_*S_)   /* 1280 rows */
#define NS  4         /* samples per LSTM resume block */
#define SPLITK_W2 4

typedef unsigned long long ull;

// ---------------- scratch (static device globals; no allocation) ----------------
__device__ float  g_x [M_*D_];     // residual stream (fp32)
__device__ float  g_xg[M_*G4_];    // gate projections, layout [(s*16+b)*256+g]
__device__ float  g_ckh[S_*B_*H_], g_ckc[S_*B_*H_]; // LSTM checkpoints
__device__ float  g_part[SPLITK_W2*M_*D_];          // w2 split-K partials
__device__ __half g_xn[M_*D_];     // layernorm out (fp16)
__device__ __half g_yq[M_*DI_];    // FFN hidden (fp16)
__device__ __half g_hq[M_*H_];     // LSTM hidden (fp16)
__device__ __half g_wih16[L_*G4_*D_];
__device__ __half g_wfc16[L_*D_*H_];
__device__ __half g_w116[L_*DI_*D_];
__device__ __half g_w216[L_*D_*DI_];

// ---------------- small helpers ----------------
__device__ __forceinline__ float fast_ex2(float x) {
    float r; asm("ex2.approx.f32 %0, %1;" : "=f"(r) : "f"(x)); return r;
}
__device__ __forceinline__ float fast_rcp(float x) {
    float r; asm("rcp.approx.f32 %0, %1;" : "=f"(r) : "f"(x)); return r;
}
__device__ __forceinline__ float sigf(float x) {
    return fast_rcp(1.0f + fast_ex2(-1.4426950408889634f * x));
}
__device__ __forceinline__ float tanhf_(float x) {
    return fmaf(2.0f, sigf(2.0f * x), -1.0f);
}
__device__ __forceinline__ uint32_t s2u(const void* p) {
    uint32_t a; asm("{ .reg .u64 t; cvta.to.shared.u64 t, %1; cvt.u32.u64 %0, t; }"
                    : "=r"(a) : "l"(p)); return a;
}
__device__ __forceinline__ void cpasync16(uint32_t d, const void* s) {
    asm volatile("cp.async.ca.shared.global [%0], [%1], 16;" :: "r"(d), "l"(s));
}
__device__ __forceinline__ void cp_commit() {
    asm volatile("cp.async.commit_group;" ::: "memory");
}
// non-trans ldmatrix x4 — A (row-major [m][k]) and B ([n][k] = col-major operand)
__device__ __forceinline__ void ldm4(uint32_t* r, uint32_t addr) {
    asm volatile("ldmatrix.sync.aligned.m8n8.x4.shared.b16 {%0,%1,%2,%3}, [%4];"
                 : "=r"(r[0]), "=r"(r[1]), "=r"(r[2]), "=r"(r[3]) : "r"(addr));
}
__device__ __forceinline__ void mma16816(float* c, const uint32_t* a, const uint32_t* b) {
    asm volatile("mma.sync.aligned.m16n8k16.row.col.f32.f16.f16.f32 "
                 "{%0,%1,%2,%3}, {%4,%5,%6,%7}, {%8,%9}, {%0,%1,%2,%3};"
                 : "+f"(c[0]), "+f"(c[1]), "+f"(c[2]), "+f"(c[3])
                 : "r"(a[0]), "r"(a[1]), "r"(a[2]), "r"(a[3]), "r"(b[0]), "r"(b[1]));
}

// ---------------- one merged fp32->fp16 weight convert ----------------
__global__ void __launch_bounds__(256) conv16_all(
    const float* s0, __half* d0, int n0,
    const float* s1, __half* d1, int n1,
    const float* s2, __half* d2, int n2,
    const float* s3, __half* d3, int n3)
{
    int i = blockIdx.x * blockDim.x + threadIdx.x;
    const float* s; __half* d;
    if (i < n0) { s = s0; d = d0; }
    else if ((i -= n0) < n1) { s = s1; d = d1; }
    else if ((i -= n1) < n2) { s = s2; d = d2; }
    else if ((i -= n2) < n3) { s = s3; d = d3; }
    else return;
    const float4 v = ((const float4*)s)[i];
    half2 a = __floats2half2_rn(v.x, v.y);
    half2 b = __floats2half2_rn(v.z, v.w);
    ((uint2*)d)[i] = make_uint2(*(uint32_t*)&a, *(uint32_t*)&b);
}

// ------- layernorm -> fp16 (optionally fusing w2 split-K reduce into x) -------
__global__ void __launch_bounds__(128) ln_kernel(
    float* __restrict__ x, __half* __restrict__ y,
    const float* __restrict__ gw, const float* __restrict__ bw,
    const float* __restrict__ part, const float* __restrict__ bias2)
{
    const int row = blockIdx.x, t = threadIdx.x;
    float4 v = *(const float4*)(x + (size_t)row * D_ + t * 4);
    if (part) {
        const float4 b = *(const float4*)(bias2 + t * 4);
        v.x += b.x; v.y += b.y; v.z += b.z; v.w += b.w;
#pragma unroll
        for (int z = 0; z < SPLITK_W2; z++) {
            const float4 p = *(const float4*)(part + (size_t)z * M_ * D_
                                              + (size_t)row * D_ + t * 4);
            v.x += p.x; v.y += p.y; v.z += p.z; v.w += p.w;
        }
        *(float4*)(x + (size_t)row * D_ + t * 4) = v;
    }
    float s  = v.x + v.y + v.z + v.w;
    float ss = v.x*v.x + v.y*v.y + v.z*v.z + v.w*v.w;
#pragma unroll
    for (int o = 16; o > 0; o >>= 1) {
        s  += __shfl_xor_sync(0xffffffffu, s,  o);
        ss += __shfl_xor_sync(0xffffffffu, ss, o);
    }
    __shared__ float rs[4], rss[4];
    const int w = t >> 5, lane = t & 31;
    if (lane == 0) { rs[w] = s; rss[w] = ss; }
    __syncthreads();
    s  = rs[0] + rs[1] + rs[2] + rs[3];
    ss = rss[0] + rss[1] + rss[2] + rss[3];
    const float mean = s * (1.0f / D_);
    const float var  = ss * (1.0f / D_) - mean * mean;
    const float rstd = rsqrtf(var + 1e-6f);
    const float4 g4 = *(const float4*)(gw + t * 4);
    const float4 b4 = *(const float4*)(bw + t * 4);
    half2 o01 = __floats2half2_rn((v.x - mean) * rstd * g4.x + b4.x,
                                  (v.y - mean) * rstd * g4.y + b4.y);
    half2 o23 = __floats2half2_rn((v.z - mean) * rstd * g4.z + b4.z,
                                  (v.w - mean) * rstd * g4.w + b4.w);
    *(uint2*)(y + (size_t)row * D_ + t * 4) =
        make_uint2(*(uint32_t*)&o01, *(uint32_t*)&o23);
}

// ------- final layernorm + projection (fusing last w2 reduce) -------
__global__ void __launch_bounds__(128) final_kernel(
    const float* __restrict__ x, const float* __restrict__ gw,
    const float* __restrict__ bw, const float* __restrict__ wp,
    const float* __restrict__ part, const float* __restrict__ bias2,
    float* __restrict__ out)
{
    const int row = blockIdx.x, t = threadIdx.x;
    float4 v = *(const float4*)(x + (size_t)row * D_ + t * 4);
    {
        const float4 b = *(const float4*)(bias2 + t * 4);
        v.x += b.x; v.y += b.y; v.z += b.z; v.w += b.w;
#pragma unroll
        for (int z = 0; z < SPLITK_W2; z++) {
            const float4 p = *(const float4*)(part + (size_t)z * M_ * D_
                                              + (size_t)row * D_ + t * 4);
            v.x += p.x; v.y += p.y; v.z += p.z; v.w += p.w;
        }
    }
    float s  = v.x + v.y + v.z + v.w;
    float ss = v.x*v.x + v.y*v.y + v.z*v.z + v.w*v.w;
#pragma unroll
    for (int o = 16; o > 0; o >>= 1) {
        s  += __shfl_xor_sync(0xffffffffu, s,  o);
        ss += __shfl_xor_sync(0xffffffffu, ss, o);
    }
    __shared__ float rs[4], rss[4], rd[4];
    const int w = t >> 5, lane = t & 31;
    if (lane == 0) { rs[w] = s; rss[w] = ss; }
    __syncthreads();
    s  = rs[0] + rs[1] + rs[2] + rs[3];
    ss = rss[0] + rss[1] + rss[2] + rss[3];
    const float mean = s * (1.0f / D_);
    const float var  = ss * (1.0f / D_) - mean * mean;
    const float rstd = rsqrtf(var + 1e-6f);
    const float4 g4 = *(const float4*)(gw + t * 4);
    const float4 b4 = *(const float4*)(bw + t * 4);
    const float4 w4 = *(const float4*)(wp + t * 4);
    float d = ((v.x - mean) * rstd * g4.x + b4.x) * w4.x
            + ((v.y - mean) * rstd * g4.y + b4.y) * w4.y
            + ((v.z - mean) * rstd * g4.z + b4.z) * w4.z
            + ((v.w - mean) * rstd * g4.w + b4.w) * w4.w;
#pragma unroll
    for (int o = 16; o > 0; o >>= 1) d += __shfl_xor_sync(0xffffffffu, d, o);
    if (lane == 0) rd[w] = d;
    __syncthreads();
    if (t == 0) out[row] = rd[0] + rd[1] + rd[2] + rd[3];
}

// ========== fp16 GEMM: C = A(MxK) * B(NxK)^T, fp32 accum ======================
// K-major, row stride KROW elements. cp.async 3-stage, 1 barrier per chunk.
// KC=64 fp16 elements = 128B rows (4 k-steps per chunk).
#define SST  144   /* smem row stride bytes: 144 = 9 x 16B -> 8 rows walk 8 banks */

template<int TM, int TN, int NTHR,
         bool BIAS, bool RELU, bool RESID, bool APERM, bool CPERM, bool OUTH, bool PART>
__global__ void __launch_bounds__(NTHR) hgemm(
    const __half* __restrict__ A, const __half* __restrict__ Bm,
    const float* __restrict__ bias, const float* __restrict__ resid,
    float* __restrict__ C, __half* __restrict__ Ch,
    int K, int KROW, int N)
{
    constexpr int WGN = NTHR / 64;
    constexpr int WM = TM / 2, WN = TN / WGN;
    constexpr int MFRAG = WM / 16, NFRAG = WN / 8;
    constexpr int BOFF = TM * SST;
    constexpr int SSZ = (TM + TN) * SST;
    constexpr int RPI = NTHR / 8;
    constexpr int AIT = (TM + RPI - 1) / RPI, BIT = (TN + RPI - 1) / RPI;

    extern __shared__ char smem[];
    const uint32_t sb = s2u(smem);
    const int tid = threadIdx.x;
    const int lane = tid & 31, warp = tid >> 5;
    const int m0 = blockIdx.y * TM, n0 = blockIdx.x * TN;
    const int wmo = (warp & 1) * WM, wno = (warp >> 1) * WN;
    const int k0 = PART ? blockIdx.z * K : 0;

    // ---- loader setup ----
    const int lrow = tid >> 3;
    const int lseg = (tid & 7) << 4;
    const char* ag[AIT]; uint32_t sa[AIT]; bool aok[AIT];
#pragma unroll
    for (int it = 0; it < AIT; it++) {
        const int r = lrow + it * RPI;
        aok[it] = (r < TM);
        const int rr = aok[it] ? r : 0;
        int am = m0 + rr;
        if (APERM) am = (am % S_) * B_ + am / S_;
        ag[it] = (const char*)A + ((size_t)am * KROW + k0) * 2 + lseg;
        sa[it] = (uint32_t)rr * SST + lseg;
    }
    const char* bg[BIT]; uint32_t sbo[BIT]; bool bok[BIT];
#pragma unroll
    for (int it = 0; it < BIT; it++) {
        const int r = lrow + it * RPI;
        bok[it] = (r < TN);
        const int rr = bok[it] ? r : 0;
        bg[it]  = (const char*)Bm + ((size_t)(n0 + rr) * KROW + k0) * 2 + lseg;
        sbo[it] = (uint32_t)rr * SST + lseg;
    }

    auto load_chunk = [&](int chunk, uint32_t st) {
        const size_t ko = (size_t)chunk * 128;
#pragma unroll
        for (int it = 0; it < AIT; it++)
            if (aok[it]) cpasync16(st + sa[it], ag[it] + ko);
#pragma unroll
        for (int it = 0; it < BIT; it++)
            if (bok[it]) cpasync16(st + BOFF + sbo[it], bg[it] + ko);
    };

    float c[MFRAG][NFRAG][4];
#pragma unroll
    for (int i = 0; i < MFRAG; i++)
#pragma unroll
        for (int j = 0; j < NFRAG; j++)
#pragma unroll
            for (int q = 0; q < 4; q++) c[i][j][q] = 0.0f;

    const int nc = K >> 6;

    load_chunk(0, sb);
    cp_commit();
    if (nc > 1) load_chunk(1, sb + SSZ);
    cp_commit();

    const uint32_t aRow = (uint32_t)(wmo + (lane & 15)) * SST + ((lane >> 4) << 4);
    const uint32_t bRow = (uint32_t)(wno + (lane & 7) + ((lane >> 4) & 1) * 8) * SST
                        + (((lane >> 3) & 1) << 4);

    for (int cc = 0; cc < nc; cc++) {
        asm volatile("cp.async.wait_group 1;" ::: "memory");
        __syncthreads();
        if (cc + 2 < nc) load_chunk(cc + 2, sb + ((cc + 2) % 3) * SSZ);
        cp_commit();

        const uint32_t st = sb + (cc % 3) * SSZ;
#pragma unroll
        for (int ks = 0; ks < 4; ks++) {
            const uint32_t kb = ks << 5;
            uint32_t a[MFRAG][4], b[NFRAG][2];
#pragma unroll
            for (int im = 0; im < MFRAG; im++)
                ldm4(a[im], st + aRow + (uint32_t)(im * 16) * SST + kb);
#pragma unroll
            for (int nf2 = 0; nf2 < NFRAG / 2; nf2++) {
                uint32_t r[4];
                ldm4(r, st + BOFF + bRow + (uint32_t)(nf2 * 16) * SST + kb);
                b[2*nf2][0] = r[0]; b[2*nf2][1] = r[1];
                b[2*nf2+1][0] = r[2]; b[2*nf2+1][1] = r[3];
            }
#pragma unroll
            for (int im = 0; im < MFRAG; im++)
#pragma unroll
                for (int nf = 0; nf < NFRAG; nf++)
                    mma16816(c[im][nf], a[im], b[nf]);
        }
    }

    // ---- epilogue ----
    float* Cp = PART ? (C + (size_t)blockIdx.z * M_ * N) : C;
#pragma unroll
    for (int im = 0; im < MFRAG; im++) {
        const int rbase = m0 + wmo + im * 16 + (lane >> 2);
#pragma unroll
        for (int half_ = 0; half_ < 2; half_++) {
            const int m = rbase + half_ * 8;
            const int cm = CPERM ? ((m % S_) * B_ + m / S_) : m;
#pragma unroll
            for (int nf = 0; nf < NFRAG; nf++) {
                const int n = n0 + wno + nf * 8 + ((lane & 3) << 1);
                float v0 = c[im][nf][half_ * 2];
                float v1 = c[im][nf][half_ * 2 + 1];
                if (BIAS)  { const float2 bq = *(const float2*)(bias + n); v0 += bq.x; v1 += bq.y; }
                if (RELU)  { v0 = fmaxf(v0, 0.0f); v1 = fmaxf(v1, 0.0f); }
                if (RESID) { const float2 rq = *(const float2*)(resid + (size_t)m * N + n); v0 += rq.x; v1 += rq.y; }
                if (OUTH) {
                    half2 hv = __floats2half2_rn(v0, v1);
                    *(uint32_t*)(Ch + (size_t)cm * N + n) = *(uint32_t*)&hv;
                } else {
                    *(float2*)(Cp + (size_t)cm * N + n) = make_float2(v0, v1);
                }
            }
        }
    }
}

// ============ LSTM phase 1: identity run, checkpoint every step ==============
__global__ void __launch_bounds__(256) lstm_base(
    const float* __restrict__ gx, const float* __restrict__ whh,
    float* __restrict__ ckh, float* __restrict__ ckc, __half* __restrict__ hq)
{
    const int b = blockIdx.x, tid = threadIdx.x;

    ull w[32];
    {
        const ulonglong2* wp = (const ulonglong2*)(whh + (size_t)tid * H_);
#pragma unroll
        for (int j = 0; j < 16; j++) {
            const ulonglong2 q = wp[j];
            w[2 * j] = q.x; w[2 * j + 1] = q.y;
        }
    }

    __shared__ __align__(16) float sh[H_];
    __shared__ float sgate[G4_];

    float c = 0.0f, hval = 0.0f;
    if (tid < H_) sh[tid] = 0.0f;
    __syncthreads();

    float gnext = __ldg(gx + ((size_t)b) * G4_ + tid);   // t = 0
    for (int t = 0; t < S_; t++) {
        if (tid < H_) {
            const size_t o = ((size_t)t * B_ + b) * H_ + tid;
            ckh[o] = hval; ckc[o] = c;
        }
        const float gxv = gnext;
        if (t + 1 < S_)   // prefetch next step's gate input (covers L2 latency)
            gnext = __ldg(gx + ((size_t)(t + 1) * B_ + b) * G4_ + tid);
        {
            const ulonglong2* hp = (const ulonglong2*)sh;
            ull a0 = 0ull, a1 = 0ull;
#pragma unroll
            for (int j = 0; j < 16; j++) {
                const ulonglong2 q = hp[j];
                asm("fma.rn.f32x2 %0, %1, %2, %0;" : "+l"(a0) : "l"(w[2*j]),   "l"(q.x));
                asm("fma.rn.f32x2 %0, %1, %2, %0;" : "+l"(a1) : "l"(w[2*j+1]), "l"(q.y));
            }
            float p0x, p0y, p1x, p1y;
            asm("mov.b64 {%0, %1}, %2;" : "=f"(p0x), "=f"(p0y) : "l"(a0));
            asm("mov.b64 {%0, %1}, %2;" : "=f"(p1x), "=f"(p1y) : "l"(a1));
            sgate[tid] = gxv + (p0x + p0y) + (p1x + p1y);
        }
        __syncthreads();
        if (tid < H_) {
            const float iv = sgate[tid];
            const float fv = sgate[64 + tid];
            const float gv = sgate[128 + tid];
            const float ov = sgate[192 + tid];
            c    = sigf(fv) * c + sigf(iv) * tanhf_(gv);
            hval = sigf(ov) * tanhf_(c);
            sh[tid] = hval;
        }
        __syncthreads();
    }
    if (tid < H_)
        hq[((size_t)(S_ - 1) * B_ + b) * H_ + tid] = __float2half_rn(hval);
}

// ============ LSTM phase 2: resume from checkpoint i, steps i..79 =============
__global__ void __launch_bounds__(256) lstm_resume(
    const float* __restrict__ gx, const float* __restrict__ whh,
    const float* __restrict__ ckh, const float* __restrict__ ckc,
    __half* __restrict__ hq)
{
    const int tid = threadIdx.x;
    const int i = blockIdx.x >> 2;
    const int g = blockIdx.x & 3;

    ull w[32];
    {
        const ulonglong2* wp = (const ulonglong2*)(whh + (size_t)tid * H_);
#pragma unroll
        for (int j = 0; j < 16; j++) {
            const ulonglong2 q = wp[j];
            w[2 * j] = q.x; w[2 * j + 1] = q.y;
        }
    }

    __shared__ __align__(16) float sh[NS][H_];
    __shared__ float sgate[NS][G4_];

    const int my_s = tid >> 6, my_k = tid & 63;
    const int my_b = g * NS + my_s;
    float c, hval;
    {
        const size_t o = ((size_t)i * B_ + my_b) * H_ + my_k;
        hval = ckh[o]; c = ckc[o];
        sh[my_s][my_k] = hval;
    }
    __syncthreads();

    float gnext[NS];   // prefetch t = i (src = 79)
#pragma unroll
    for (int s = 0; s < NS; s++)
        gnext[s] = __ldg(gx + ((size_t)(S_ - 1) * B_ + g * NS + s) * G4_ + tid);

    for (int t = i; t < S_; t++) {
        float gxv[NS];
#pragma unroll
        for (int s = 0; s < NS; s++) gxv[s] = gnext[s];
        if (t + 1 < S_) {
            const int t1 = t + 1;
            const int src1 = (t1 == S_ - 1) ? i : t1;   // t1 > i always
#pragma unroll
            for (int s = 0; s < NS; s++)
                gnext[s] = __ldg(gx + ((size_t)src1 * B_ + g * NS + s) * G4_ + tid);
        }
#pragma unroll
        for (int s = 0; s < NS; s++) {
            const ulonglong2* hp = (const ulonglong2*)sh[s];
            ull a0 = 0ull, a1 = 0ull;
#pragma unroll
            for (int j = 0; j < 16; j++) {
                const ulonglong2 q = hp[j];
                asm("fma.rn.f32x2 %0, %1, %2, %0;" : "+l"(a0) : "l"(w[2*j]),   "l"(q.x));
                asm("fma.rn.f32x2 %0, %1, %2, %0;" : "+l"(a1) : "l"(w[2*j+1]), "l"(q.y));
            }
            float p0x, p0y, p1x, p1y;
            asm("mov.b64 {%0, %1}, %2;" : "=f"(p0x), "=f"(p0y) : "l"(a0));
            asm("mov.b64 {%0, %1}, %2;" : "=f"(p1x), "=f"(p1y) : "l"(a1));
            sgate[s][tid] = gxv[s] + (p0x + p0y) + (p1x + p1y);
        }
        __syncthreads();
        const float iv = sgate[my_s][my_k];
        const float fv = sgate[my_s][64 + my_k];
        const float gv = sgate[my_s][128 + my_k];
        const float ov = sgate[my_s][192 + my_k];
        c    = sigf(fv) * c + sigf(iv) * tanhf_(gv);
        hval = sigf(ov) * tanhf_(c);
        sh[my_s][my_k] = hval;
        __syncthreads();
    }
    hq[((size_t)i * B_ + my_b) * H_ + my_k] = __float2half_rn(hval);
}

// ---------------- launch ----------------
#define SMEM_T(TM, TN) (3 * ((TM) + (TN)) * SST)

extern "C" void kernel_launch(void* const* d_in, const int* in_sizes, int n_in,
                              void* d_out, int out_size)
{
    const float* src  = (const float*)d_in[0];
    const float* ln1g = (const float*)d_in[2];
    const float* ln1b = (const float*)d_in[3];
    const float* wih  = (const float*)d_in[4];
    const float* whh  = (const float*)d_in[5];
    const float* wfc  = (const float*)d_in[6];
    const float* ln2g = (const float*)d_in[7];
    const float* ln2b = (const float*)d_in[8];
    const float* w1   = (const float*)d_in[9];
    const float* b1   = (const float*)d_in[10];
    const float* w2   = (const float*)d_in[11];
    const float* b2   = (const float*)d_in[12];
    const float* lnfg = (const float*)d_in[13];
    const float* lnfb = (const float*)d_in[14];
    const float* wprj = (const float*)d_in[15];
    float* out = (float*)d_out;

    float *px, *pxg, *pckh, *pckc, *ppart;
    __half *pxn, *pyq, *phq, *pwih16, *pwfc16, *pw116, *pw216;
    cudaGetSymbolAddress((void**)&px,   g_x);
    cudaGetSymbolAddress((void**)&pxg,  g_xg);
    cudaGetSymbolAddress((void**)&pckh, g_ckh);  cudaGetSymbolAddress((void**)&pckc, g_ckc);
    cudaGetSymbolAddress((void**)&ppart, g_part);
    cudaGetSymbolAddress((void**)&pxn,  g_xn);
    cudaGetSymbolAddress((void**)&pyq,  g_yq);
    cudaGetSymbolAddress((void**)&phq,  g_hq);
    cudaGetSymbolAddress((void**)&pwih16, g_wih16);
    cudaGetSymbolAddress((void**)&pwfc16, g_wfc16);
    cudaGetSymbolAddress((void**)&pw116,  g_w116);
    cudaGetSymbolAddress((void**)&pw216,  g_w216);

    auto kwih = hgemm<32, 32, 128, false, false, false, false, true,  false, false>;
    auto kfc  = hgemm<64, 64, 128, false, false, true,  true,  false, false, false>;
    auto kw1  = hgemm<64, 128,128, true,  true,  false, false, false, true,  false>;
    auto kw2  = hgemm<64, 128,128, false, false, false, false, false, false, true >;

    cudaFuncSetAttribute(kwih, cudaFuncAttributeMaxDynamicSharedMemorySize, SMEM_T(32, 32));
    cudaFuncSetAttribute(kfc,  cudaFuncAttributeMaxDynamicSharedMemorySize, SMEM_T(64, 64));
    cudaFuncSetAttribute(kw1,  cudaFuncAttributeMaxDynamicSharedMemorySize, SMEM_T(64, 128));
    cudaFuncSetAttribute(kw2,  cudaFuncAttributeMaxDynamicSharedMemorySize, SMEM_T(64, 128));

    cudaMemcpyAsync(px, src, (size_t)M_ * D_ * sizeof(float),
                    cudaMemcpyDeviceToDevice, 0);

    // all weight conversions in ONE kernel
    const int nwih = L_*G4_*D_/4, nwfc = L_*D_*H_/4,
              nw1 = L_*DI_*D_/4,  nw2 = L_*D_*DI_/4;
    conv16_all<<<(nwih + nwfc + nw1 + nw2 + 255)/256, 256>>>(
        wih, pwih16, nwih, wfc, pwfc16, nwfc, w1, pw116, nw1, w2, pw216, nw2);

    for (int l = 0; l < L_; l++) {
        // ln1 — for l>0 also folds in layer l-1's w2 split-K reduce + b2
        ln_kernel<<<M_, 128>>>(px, pxn, ln1g + l * D_, ln1b + l * D_,
                               l == 0 ? nullptr : ppart,
                               l == 0 ? nullptr : (b2 + (l - 1) * D_));
        // xg[s,b,:] = xn @ wih^T  (CPERM) — grid 8x40 = 320
        kwih<<<dim3(G4_/32, M_/32), 128, SMEM_T(32, 32)>>>(
            pxn, pwih16 + (size_t)l*G4_*D_, nullptr, nullptr,
            pxg, nullptr, D_, D_, G4_);
        // Janossy LSTM
        lstm_base<<<B_, 256>>>(pxg, whh + (size_t)l*G4_*H_, pckh, pckc, phq);
        lstm_resume<<<(S_-1)*(B_/NS), 256>>>(pxg, whh + (size_t)l*G4_*H_,
                                             pckh, pckc, phq);
        // x += h @ wfc^T  (APERM + RESID) — grid 8x20 = 160
        kfc<<<dim3(D_/64, M_/64), 128, SMEM_T(64, 64)>>>(
            phq, pwfc16 + (size_t)l*D_*H_, nullptr, px,
            px, nullptr, H_, H_, D_);
        ln_kernel<<<M_, 128>>>(px, pxn, ln2g + l * D_, ln2b + l * D_,
                               nullptr, nullptr);
        // y = relu(xn @ w1^T + b1) -> fp16 — grid 16x20 = 320
        kw1<<<dim3(DI_/128, M_/64), 128, SMEM_T(64, 128)>>>(
            pxn, pw116 + (size_t)l*DI_*D_, b1 + l*DI_, nullptr,
            nullptr, pyq, D_, D_, DI_);
        // w2 split-K partials — grid 4x20x4 = 320 (reduced in next ln1/final)
        kw2<<<dim3(D_/128, M_/64, SPLITK_W2), 128, SMEM_T(64, 128)>>>(
            pyq, pw216 + (size_t)l*D_*DI_, nullptr, nullptr,
            ppart, nullptr, DI_/SPLITK_W2, DI_, D_);
    }
    final_kernel<<<M_, 128>>>(px, lnfg, lnfb, wprj,
                              ppart, b2 + (L_ - 1) * D_, out);
}